// round 11
// baseline (speedup 1.0000x reference)
#include <cuda_runtime.h>
#include <math.h>

// ---- problem constants ----
#define HID    2048
#define NH     32
#define KVH    8
#define HD     64
#define BATCH  2
#define SEQ    2048
#define MROWS  (BATCH * SEQ)   // 4096
#define KVDIM  (KVH * HD)      // 512

// ---- scratch (device globals: allocation-free) ----
__device__ float g_q[(size_t)MROWS * HID];
__device__ float g_k[(size_t)MROWS * KVDIM];
__device__ float g_v[(size_t)MROWS * KVDIM];

__device__ float g_xh[(size_t)MROWS * HID],   g_xl[(size_t)MROWS * HID];
__device__ float g_wqh[(size_t)HID * HID],    g_wql[(size_t)HID * HID];
__device__ float g_wkh[(size_t)HID * KVDIM],  g_wkl[(size_t)HID * KVDIM];
__device__ float g_wvh[(size_t)HID * KVDIM],  g_wvl[(size_t)HID * KVDIM];
__device__ float g_woh[(size_t)HID * HID],    g_wol[(size_t)HID * HID];
__device__ float g_kh[(size_t)MROWS * KVDIM], g_kl[(size_t)MROWS * KVDIM];
__device__ float g_vh[(size_t)MROWS * KVDIM], g_vl[(size_t)MROWS * KVDIM];
__device__ float g_atth[(size_t)MROWS * HID], g_attl[(size_t)MROWS * HID];

// ---- tf32 helpers ----
__device__ __forceinline__ unsigned to_tf32(float x) {
    unsigned r;
    asm("cvt.rna.tf32.f32 %0, %1;" : "=r"(r) : "f"(x));
    return r;
}
__device__ __forceinline__ void split_tf32(float x, unsigned& hi, unsigned& lo) {
    hi = to_tf32(x);
    lo = to_tf32(x - __uint_as_float(hi));
}
// D += A(16x8 row) @ B(8x8 col), tf32 in / f32 accum
__device__ __forceinline__ void mma_tf32(float* c, const unsigned* a, const unsigned* b) {
    asm volatile(
        "mma.sync.aligned.m16n8k8.row.col.f32.tf32.tf32.f32 "
        "{%0,%1,%2,%3}, {%4,%5,%6,%7}, {%8,%9}, {%0,%1,%2,%3};"
        : "+f"(c[0]), "+f"(c[1]), "+f"(c[2]), "+f"(c[3])
        : "r"(a[0]), "r"(a[1]), "r"(a[2]), "r"(a[3]), "r"(b[0]), "r"(b[1]));
}

// ============================================================
// split: in (fp32) -> hi/lo tf32-representable fp32 arrays.
// n divisible by 1024.
// ============================================================
__global__ void split_kernel(const float* __restrict__ in,
                             float* __restrict__ hi, float* __restrict__ lo, int n)
{
    int i = (blockIdx.x * blockDim.x + threadIdx.x) * 4;
    if (i >= n) return;
    float4 v = *(const float4*)&in[i];
    float vv[4] = {v.x, v.y, v.z, v.w};
    float hv[4], lv[4];
#pragma unroll
    for (int j = 0; j < 4; ++j) {
        unsigned h, l;
        split_tf32(vv[j], h, l);
        hv[j] = __uint_as_float(h);
        lv[j] = __uint_as_float(l);
    }
    *(float4*)&hi[i] = make_float4(hv[0], hv[1], hv[2], hv[3]);
    *(float4*)&lo[i] = make_float4(lv[0], lv[1], lv[2], lv[3]);
}

// ============================================================
// GEMM on pre-split operands: C = A @ B, A=[M,K], B=[K,N] row-major.
// 128x128 tile, BK=16, 256 thr = 8 warps (4M x 2N). tf32x2 MMA.
// ============================================================
__global__ void __launch_bounds__(256)
gemm_ps_kernel(const float* __restrict__ Ah, const float* __restrict__ Al,
               const float* __restrict__ Bh, const float* __restrict__ Bl,
               float* __restrict__ C, int M, int N, int K)
{
    __shared__ float Ash[16][132];   // [k][m] hi
    __shared__ float Asl[16][132];   // [k][m] lo
    __shared__ float Bsh[16][132];   // [k][n] hi
    __shared__ float Bsl[16][132];   // [k][n] lo

    const int tid  = threadIdx.x;
    const int lane = tid & 31;
    const int wid  = tid >> 5;
    const int g    = lane >> 2;
    const int q4   = lane & 3;
    const int warpM = wid >> 1;
    const int warpN = wid & 1;
    const int rowBase = blockIdx.y * 128;
    const int colBase = blockIdx.x * 128;

    float acc[2][8][4] = {};

    for (int kt = 0; kt < K; kt += 16) {
        __syncthreads();
#pragma unroll
        for (int p = 0; p < 2; ++p) {
            int id = tid + p * 256;
            int ar = id >> 2;
            int ac = (id & 3) * 4;
            size_t off = (size_t)(rowBase + ar) * K + kt + ac;
            float4 vh = *(const float4*)&Ah[off];
            float4 vl = *(const float4*)&Al[off];
            Ash[ac + 0][ar] = vh.x; Ash[ac + 1][ar] = vh.y;
            Ash[ac + 2][ar] = vh.z; Ash[ac + 3][ar] = vh.w;
            Asl[ac + 0][ar] = vl.x; Asl[ac + 1][ar] = vl.y;
            Asl[ac + 2][ar] = vl.z; Asl[ac + 3][ar] = vl.w;
        }
#pragma unroll
        for (int p = 0; p < 2; ++p) {
            int id = tid + p * 256;
            int br = id >> 5;
            int bc = (id & 31) * 4;
            size_t off = (size_t)(kt + br) * N + colBase + bc;
            *(float4*)&Bsh[br][bc] = *(const float4*)&Bh[off];
            *(float4*)&Bsl[br][bc] = *(const float4*)&Bl[off];
        }
        __syncthreads();

#pragma unroll
        for (int ks = 0; ks < 2; ++ks) {
            const int k0 = ks * 8 + q4;
            unsigned ah[2][4], al[2][4];
#pragma unroll
            for (int mt = 0; mt < 2; ++mt) {
                int m0 = warpM * 32 + mt * 16 + g;
                ah[mt][0] = __float_as_uint(Ash[k0][m0]);
                ah[mt][1] = __float_as_uint(Ash[k0][m0 + 8]);
                ah[mt][2] = __float_as_uint(Ash[k0 + 4][m0]);
                ah[mt][3] = __float_as_uint(Ash[k0 + 4][m0 + 8]);
                al[mt][0] = __float_as_uint(Asl[k0][m0]);
                al[mt][1] = __float_as_uint(Asl[k0][m0 + 8]);
                al[mt][2] = __float_as_uint(Asl[k0 + 4][m0]);
                al[mt][3] = __float_as_uint(Asl[k0 + 4][m0 + 8]);
            }
#pragma unroll
            for (int nt = 0; nt < 8; ++nt) {
                int n0 = warpN * 64 + nt * 8 + g;
                unsigned bh[2] = {__float_as_uint(Bsh[k0][n0]),
                                  __float_as_uint(Bsh[k0 + 4][n0])};
                unsigned bl[2] = {__float_as_uint(Bsl[k0][n0]),
                                  __float_as_uint(Bsl[k0 + 4][n0])};
#pragma unroll
                for (int mt = 0; mt < 2; ++mt) {
                    mma_tf32(acc[mt][nt], ah[mt], bh);
                    mma_tf32(acc[mt][nt], al[mt], bh);
                    mma_tf32(acc[mt][nt], ah[mt], bl);
                }
            }
        }
    }

#pragma unroll
    for (int mt = 0; mt < 2; ++mt) {
        int row = rowBase + warpM * 32 + mt * 16 + g;
#pragma unroll
        for (int nt = 0; nt < 8; ++nt) {
            int col = colBase + warpN * 64 + nt * 8 + 2 * q4;
            *(float2*)&C[(size_t)row * N + col] =
                make_float2(acc[mt][nt][0], acc[mt][nt][1]);
            *(float2*)&C[(size_t)(row + 8) * N + col] =
                make_float2(acc[mt][nt][2], acc[mt][nt][3]);
        }
    }
}

// ============================================================
// RoPE in place on q [MROWS, NH*HD] and k [MROWS, KVH*HD].
// ============================================================
__global__ void rope_kernel(float* __restrict__ q, float* __restrict__ k)
{
    const int QP = MROWS * NH * (HD / 2);
    const int KP = MROWS * KVH * (HD / 2);
    int idx = blockIdx.x * blockDim.x + threadIdx.x;
    if (idx >= QP + KP) return;

    float* buf;
    int row, head, j, rowdim;
    if (idx < QP) {
        int t = idx;
        j = t & 31; t >>= 5;
        head = t & (NH - 1); t >>= 5;
        row = t;
        buf = q; rowdim = NH * HD;
    } else {
        int t = idx - QP;
        j = t & 31; t >>= 5;
        head = t & (KVH - 1); t >>= 3;
        row = t;
        buf = k; rowdim = KVH * HD;
    }
    int pos = row & (SEQ - 1);
    float inv_freq = exp2f(-(float)j * 0.41524101186092029f);
    float ang = (float)pos * inv_freq;
    float c, s;
    sincosf(ang, &s, &c);

    float* p = buf + (size_t)row * rowdim + head * HD + j;
    float x1 = p[0], x2 = p[32];
    p[0]  = x1 * c - x2 * s;
    p[32] = x2 * c + x1 * s;
}

// ============================================================
// Flash attention, tf32x2 MMA, pre-split K/V, register-hoisted Q.
// Grid: (SEQ/128, NH, BATCH). 256 thr = 8 warps, warp owns 16 q rows.
// Smem: QP[128][68] (Q staging, reused as P) + Kth/Ktl/Vh/Vl[64][68]
//     = 104448 bytes.
// Outputs att pre-split (atth, attl) for the wo GEMM.
// ============================================================
__global__ void __launch_bounds__(256)
attn_kernel(const float* __restrict__ q,
            const float* __restrict__ kh, const float* __restrict__ kl,
            const float* __restrict__ vh, const float* __restrict__ vl,
            float* __restrict__ atth, float* __restrict__ attl)
{
    extern __shared__ float sm[];
    float* QP  = sm;                 // [128][68]: Q staging, then P
    float* Kth = sm + 128 * 68;      // [64 d][68 key] hi
    float* Ktl = Kth + 64 * 68;
    float* Vh  = Ktl + 64 * 68;      // [64 key][68 d] hi
    float* Vl  = Vh + 64 * 68;

    const int tid  = threadIdx.x;
    const int lane = tid & 31;
    const int wid  = tid >> 5;
    const int g    = lane >> 2;
    const int q4   = lane & 3;
    const int qb   = blockIdx.x * 128;
    const int h    = blockIdx.y;
    const int b    = blockIdx.z;
    const int kvh  = h >> 2;

    const float* qg  = q  + (size_t)b * SEQ * HID + (size_t)h * HD;
    const float* kgh = kh + (size_t)b * SEQ * KVDIM + (size_t)kvh * HD;
    const float* kgl = kl + (size_t)b * SEQ * KVDIM + (size_t)kvh * HD;
    const float* vgh = vh + (size_t)b * SEQ * KVDIM + (size_t)kvh * HD;
    const float* vgl = vl + (size_t)b * SEQ * KVDIM + (size_t)kvh * HD;
    float* oh = atth + (size_t)b * SEQ * HID + (size_t)h * HD;
    float* ol = attl + (size_t)b * SEQ * HID + (size_t)h * HD;

    // stage Q tile (128x64) into QP, fold in 1/8 scale
#pragma unroll
    for (int p = 0; p < 8; ++p) {
        int id = tid + p * 256;
        int m = id >> 4, d4 = (id & 15) * 4;
        float4 vq = *(const float4*)&qg[(size_t)(qb + m) * HID + d4];
        vq.x *= 0.125f; vq.y *= 0.125f; vq.z *= 0.125f; vq.w *= 0.125f;
        *(float4*)&QP[m * 68 + d4] = vq;
    }
    __syncthreads();

    const int m0 = wid * 16 + g;   // lane-row A; row B = m0 + 8

    // hoist Q fragments + split ONCE into registers
    unsigned Qh[8][4], Ql[8][4];
#pragma unroll
    for (int kt = 0; kt < 8; ++kt) {
        int c0 = kt * 8 + q4;
        float qa[4] = {QP[m0 * 68 + c0], QP[(m0 + 8) * 68 + c0],
                       QP[m0 * 68 + c0 + 4], QP[(m0 + 8) * 68 + c0 + 4]};
#pragma unroll
        for (int j = 0; j < 4; ++j) split_tf32(qa[j], Qh[kt][j], Ql[kt][j]);
    }

    float Oa[8][4] = {};
    float miA = -3.0e38f, miB = -3.0e38f, liA = 0.0f, liB = 0.0f;

    for (int kb = 0; kb < SEQ; kb += 64) {
        __syncthreads();  // guards QP(Q-frag reads / P reuse) + K/V tiles
        // stage pre-split K (transposed) and V tiles
#pragma unroll
        for (int p = 0; p < 4; ++p) {
            int id = tid + p * 256;
            int n = id >> 4, d4 = (id & 15) * 4;
            size_t off = (size_t)(kb + n) * KVDIM + d4;
            float4 kvh4 = *(const float4*)&kgh[off];
            float4 kvl4 = *(const float4*)&kgl[off];
            Kth[(d4 + 0) * 68 + n] = kvh4.x; Kth[(d4 + 1) * 68 + n] = kvh4.y;
            Kth[(d4 + 2) * 68 + n] = kvh4.z; Kth[(d4 + 3) * 68 + n] = kvh4.w;
            Ktl[(d4 + 0) * 68 + n] = kvl4.x; Ktl[(d4 + 1) * 68 + n] = kvl4.y;
            Ktl[(d4 + 2) * 68 + n] = kvl4.z; Ktl[(d4 + 3) * 68 + n] = kvl4.w;
            *(float4*)&Vh[n * 68 + d4] = *(const float4*)&vgh[off];
            *(float4*)&Vl[n * 68 + d4] = *(const float4*)&vgl[off];
        }
        __syncthreads();

        // ---- S = Q @ K^T ----
        float S[8][4] = {};
#pragma unroll
        for (int kt = 0; kt < 8; ++kt) {
            int c0 = kt * 8 + q4;
#pragma unroll
            for (int nt = 0; nt < 8; ++nt) {
                int n0 = nt * 8 + g;
                unsigned bh[2] = {__float_as_uint(Kth[c0 * 68 + n0]),
                                  __float_as_uint(Kth[(c0 + 4) * 68 + n0])};
                unsigned bl[2] = {__float_as_uint(Ktl[c0 * 68 + n0]),
                                  __float_as_uint(Ktl[(c0 + 4) * 68 + n0])};
                mma_tf32(S[nt], Qh[kt], bh);
                mma_tf32(S[nt], Ql[kt], bh);
                mma_tf32(S[nt], Qh[kt], bl);
            }
        }

        // ---- online softmax (rows m0, m0+8) ----
        float mA = -3.0e38f, mB = -3.0e38f;
#pragma unroll
        for (int nt = 0; nt < 8; ++nt) {
            mA = fmaxf(mA, fmaxf(S[nt][0], S[nt][1]));
            mB = fmaxf(mB, fmaxf(S[nt][2], S[nt][3]));
        }
        mA = fmaxf(mA, __shfl_xor_sync(0xffffffffu, mA, 1));
        mA = fmaxf(mA, __shfl_xor_sync(0xffffffffu, mA, 2));
        mB = fmaxf(mB, __shfl_xor_sync(0xffffffffu, mB, 1));
        mB = fmaxf(mB, __shfl_xor_sync(0xffffffffu, mB, 2));

        float mnA = fmaxf(miA, mA), mnB = fmaxf(miB, mB);
        float aA = __expf(miA - mnA), aB = __expf(miB - mnB);
        miA = mnA; miB = mnB;

        float sA = 0.0f, sB = 0.0f;
#pragma unroll
        for (int nt = 0; nt < 8; ++nt) {
            S[nt][0] = __expf(S[nt][0] - mnA);
            S[nt][1] = __expf(S[nt][1] - mnA);
            S[nt][2] = __expf(S[nt][2] - mnB);
            S[nt][3] = __expf(S[nt][3] - mnB);
            sA += S[nt][0] + S[nt][1];
            sB += S[nt][2] + S[nt][3];
        }
        sA += __shfl_xor_sync(0xffffffffu, sA, 1);
        sA += __shfl_xor_sync(0xffffffffu, sA, 2);
        sB += __shfl_xor_sync(0xffffffffu, sB, 1);
        sB += __shfl_xor_sync(0xffffffffu, sB, 2);
        liA = liA * aA + sA;
        liB = liB * aB + sB;

#pragma unroll
        for (int nt = 0; nt < 8; ++nt) {
            Oa[nt][0] *= aA; Oa[nt][1] *= aA;
            Oa[nt][2] *= aB; Oa[nt][3] *= aB;
            *(float2*)&QP[m0 * 68 + nt * 8 + 2 * q4] = make_float2(S[nt][0], S[nt][1]);
            *(float2*)&QP[(m0 + 8) * 68 + nt * 8 + 2 * q4] = make_float2(S[nt][2], S[nt][3]);
        }
        __syncwarp();

        // ---- O += P @ V ----
#pragma unroll
        for (int kt = 0; kt < 8; ++kt) {
            int c0 = kt * 8 + q4;
            float pa[4] = {QP[m0 * 68 + c0], QP[(m0 + 8) * 68 + c0],
                           QP[m0 * 68 + c0 + 4], QP[(m0 + 8) * 68 + c0 + 4]};
            unsigned ph[4], pl[4];
#pragma unroll
            for (int j = 0; j < 4; ++j) split_tf32(pa[j], ph[j], pl[j]);
#pragma unroll
            for (int nt = 0; nt < 8; ++nt) {
                int n0 = nt * 8 + g;
                unsigned bh[2] = {__float_as_uint(Vh[c0 * 68 + n0]),
                                  __float_as_uint(Vh[(c0 + 4) * 68 + n0])};
                unsigned bl[2] = {__float_as_uint(Vl[c0 * 68 + n0]),
                                  __float_as_uint(Vl[(c0 + 4) * 68 + n0])};
                mma_tf32(Oa[nt], ph, bh);
                mma_tf32(Oa[nt], pl, bh);
                mma_tf32(Oa[nt], ph, bl);
            }
        }
    }

    // epilogue: normalize, split, store hi/lo att
    float invA = 1.0f / liA, invB = 1.0f / liB;
#pragma unroll
    for (int nt = 0; nt < 8; ++nt) {
        int col = nt * 8 + 2 * q4;
        float o0 = Oa[nt][0] * invA, o1 = Oa[nt][1] * invA;
        float o2 = Oa[nt][2] * invB, o3 = Oa[nt][3] * invB;
        unsigned h0, l0, h1, l1, h2, l2, h3, l3;
        split_tf32(o0, h0, l0); split_tf32(o1, h1, l1);
        split_tf32(o2, h2, l2); split_tf32(o3, h3, l3);
        size_t rA = (size_t)(qb + m0) * HID + col;
        size_t rB = (size_t)(qb + m0 + 8) * HID + col;
        *(float2*)&oh[rA] = make_float2(__uint_as_float(h0), __uint_as_float(h1));
        *(float2*)&ol[rA] = make_float2(__uint_as_float(l0), __uint_as_float(l1));
        *(float2*)&oh[rB] = make_float2(__uint_as_float(h2), __uint_as_float(h3));
        *(float2*)&ol[rB] = make_float2(__uint_as_float(l2), __uint_as_float(l3));
    }
}

// ============================================================
// launch
// ============================================================
extern "C" void kernel_launch(void* const* d_in, const int* in_sizes, int n_in,
                              void* d_out, int out_size)
{
    const float* x  = (const float*)d_in[0];
    const float* wq = (const float*)d_in[1];
    const float* wk = (const float*)d_in[2];
    const float* wv = (const float*)d_in[3];
    const float* wo = (const float*)d_in[4];
    float* out = (float*)d_out;

    float *qp, *kp, *vp;
    float *xh, *xl, *wqh, *wql, *wkh, *wkl, *wvh, *wvl, *woh, *wol;
    float *khp, *klp, *vhp, *vlp, *ath, *atl;
    cudaGetSymbolAddress((void**)&qp, g_q);
    cudaGetSymbolAddress((void**)&kp, g_k);
    cudaGetSymbolAddress((void**)&vp, g_v);
    cudaGetSymbolAddress((void**)&xh, g_xh);   cudaGetSymbolAddress((void**)&xl, g_xl);
    cudaGetSymbolAddress((void**)&wqh, g_wqh); cudaGetSymbolAddress((void**)&wql, g_wql);
    cudaGetSymbolAddress((void**)&wkh, g_wkh); cudaGetSymbolAddress((void**)&wkl, g_wkl);
    cudaGetSymbolAddress((void**)&wvh, g_wvh); cudaGetSymbolAddress((void**)&wvl, g_wvl);
    cudaGetSymbolAddress((void**)&woh, g_woh); cudaGetSymbolAddress((void**)&wol, g_wol);
    cudaGetSymbolAddress((void**)&khp, g_kh);  cudaGetSymbolAddress((void**)&klp, g_kl);
    cudaGetSymbolAddress((void**)&vhp, g_vh);  cudaGetSymbolAddress((void**)&vlp, g_vl);
    cudaGetSymbolAddress((void**)&ath, g_atth);cudaGetSymbolAddress((void**)&atl, g_attl);

    dim3 blk(256);

    // pre-split inputs and weights
    split_kernel<<<(MROWS * HID) / 1024, 256>>>(x, xh, xl, MROWS * HID);
    split_kernel<<<(HID * HID) / 1024, 256>>>(wq, wqh, wql, HID * HID);
    split_kernel<<<(HID * KVDIM) / 1024, 256>>>(wk, wkh, wkl, HID * KVDIM);
    split_kernel<<<(HID * KVDIM) / 1024, 256>>>(wv, wvh, wvl, HID * KVDIM);
    split_kernel<<<(HID * HID) / 1024, 256>>>(wo, woh, wol, HID * HID);

    // QKV projections
    gemm_ps_kernel<<<dim3(HID / 128, MROWS / 128), blk>>>(xh, xl, wqh, wql, qp, MROWS, HID, HID);
    gemm_ps_kernel<<<dim3(KVDIM / 128, MROWS / 128), blk>>>(xh, xl, wkh, wkl, kp, MROWS, KVDIM, HID);
    gemm_ps_kernel<<<dim3(KVDIM / 128, MROWS / 128), blk>>>(xh, xl, wvh, wvl, vp, MROWS, KVDIM, HID);

    // RoPE on q, k
    int total = MROWS * NH * (HD / 2) + MROWS * KVH * (HD / 2);
    rope_kernel<<<(total + 255) / 256, 256>>>(qp, kp);

    // split roped k and v for the attention mainloop
    split_kernel<<<(MROWS * KVDIM) / 1024, 256>>>(kp, khp, klp, MROWS * KVDIM);
    split_kernel<<<(MROWS * KVDIM) / 1024, 256>>>(vp, vhp, vlp, MROWS * KVDIM);

    // attention (emits pre-split att)
    cudaFuncSetAttribute(attn_kernel, cudaFuncAttributeMaxDynamicSharedMemorySize, 104448);
    attn_kernel<<<dim3(SEQ / 128, NH, BATCH), blk, 104448>>>(qp, khp, klp, vhp, vlp, ath, atl);

    // output projection
    gemm_ps_kernel<<<dim3(HID / 128, MROWS / 128), blk>>>(ath, atl, woh, wol, out, MROWS, HID, HID);
}

// round 12
// speedup vs baseline: 1.8856x; 1.8856x over previous
#include <cuda_runtime.h>
#include <cuda_bf16.h>
#include <math.h>

// ---- problem constants ----
#define HID    2048
#define NH     32
#define KVH    8
#define HD     64
#define BATCH  2
#define SEQ    2048
#define MROWS  (BATCH * SEQ)   // 4096
#define KVDIM  (KVH * HD)      // 512

typedef unsigned short ushortT;

// ---- scratch (device globals: allocation-free) ----
__device__ float   g_q[(size_t)MROWS * HID];
__device__ float   g_k[(size_t)MROWS * KVDIM];
__device__ float   g_v[(size_t)MROWS * KVDIM];

__device__ ushortT g_xh[(size_t)MROWS * HID],   g_xl[(size_t)MROWS * HID];
__device__ ushortT g_wqh[(size_t)HID * HID],    g_wql[(size_t)HID * HID];
__device__ ushortT g_wkh[(size_t)HID * KVDIM],  g_wkl[(size_t)HID * KVDIM];
__device__ ushortT g_wvh[(size_t)HID * KVDIM],  g_wvl[(size_t)HID * KVDIM];
__device__ ushortT g_woh[(size_t)HID * HID],    g_wol[(size_t)HID * HID];
__device__ ushortT g_kh[(size_t)MROWS * KVDIM], g_kl[(size_t)MROWS * KVDIM];
__device__ ushortT g_vh[(size_t)MROWS * KVDIM], g_vl[(size_t)MROWS * KVDIM];
__device__ ushortT g_atth[(size_t)MROWS * HID], g_attl[(size_t)MROWS * HID];

// ---- helpers ----
__device__ __forceinline__ unsigned saddr(const void* p) {
    return (unsigned)__cvta_generic_to_shared(p);
}
__device__ __forceinline__ void ldsm4(unsigned* r, unsigned a) {
    asm volatile("ldmatrix.sync.aligned.m8n8.x4.shared.b16 {%0,%1,%2,%3}, [%4];"
                 : "=r"(r[0]), "=r"(r[1]), "=r"(r[2]), "=r"(r[3]) : "r"(a));
}
__device__ __forceinline__ void ldsm4t(unsigned* r, unsigned a) {
    asm volatile("ldmatrix.sync.aligned.m8n8.x4.trans.shared.b16 {%0,%1,%2,%3}, [%4];"
                 : "=r"(r[0]), "=r"(r[1]), "=r"(r[2]), "=r"(r[3]) : "r"(a));
}
// D += A(16x16 row) @ B(16x8 col), bf16 in / f32 accum
__device__ __forceinline__ void mma_bf16(float* c, const unsigned* a, const unsigned* b) {
    asm volatile(
        "mma.sync.aligned.m16n8k16.row.col.f32.bf16.bf16.f32 "
        "{%0,%1,%2,%3}, {%4,%5,%6,%7}, {%8,%9}, {%0,%1,%2,%3};"
        : "+f"(c[0]), "+f"(c[1]), "+f"(c[2]), "+f"(c[3])
        : "r"(a[0]), "r"(a[1]), "r"(a[2]), "r"(a[3]), "r"(b[0]), "r"(b[1]));
}
// split two floats into packed bf16 hi-pair / lo-pair
__device__ __forceinline__ void split2(float a, float b, unsigned& hp, unsigned& lp) {
    __nv_bfloat16 ha = __float2bfloat16_rn(a), hb = __float2bfloat16_rn(b);
    __nv_bfloat16 la = __float2bfloat16_rn(a - __bfloat162float(ha));
    __nv_bfloat16 lb = __float2bfloat16_rn(b - __bfloat162float(hb));
    __nv_bfloat162 hv(ha, hb), lv(la, lb);
    hp = *reinterpret_cast<unsigned*>(&hv);
    lp = *reinterpret_cast<unsigned*>(&lv);
}

// ============================================================
// split fp32 -> bf16 hi / bf16 lo arrays. n divisible by 1024.
// ============================================================
__global__ void split_bf16_kernel(const float* __restrict__ in,
                                  ushortT* __restrict__ hi, ushortT* __restrict__ lo,
                                  int n)
{
    int i = (blockIdx.x * blockDim.x + threadIdx.x) * 4;
    if (i >= n) return;
    float4 v = *(const float4*)&in[i];
    unsigned h0, l0, h1, l1;
    split2(v.x, v.y, h0, l0);
    split2(v.z, v.w, h1, l1);
    *(uint2*)&hi[i] = make_uint2(h0, h1);
    *(uint2*)&lo[i] = make_uint2(l0, l1);
}

// ============================================================
// GEMM on pre-split bf16: C[M,N](f32) = A[M,K] @ B[K,N].
// 128x128 tile, BK=32, 256 thr = 8 warps (4M x 2N), bf16x3 MMA.
// Smem: A [128][56] hi/lo, B [32][136] hi/lo (all strides 16B-aligned
// and conflict-free mod 128B for ldmatrix).
// ============================================================
__global__ void __launch_bounds__(256)
gemm_bf16_kernel(const ushortT* __restrict__ Ah, const ushortT* __restrict__ Al,
                 const ushortT* __restrict__ Bh, const ushortT* __restrict__ Bl,
                 float* __restrict__ C, int M, int N, int K)
{
    __shared__ ushortT Ash[128 * 56], Asl[128 * 56];
    __shared__ ushortT Bsh[32 * 136], Bsl[32 * 136];

    const int tid  = threadIdx.x;
    const int lane = tid & 31;
    const int wid  = tid >> 5;
    const int g    = lane >> 2;
    const int q4   = lane & 3;
    const int warpM = wid >> 1;           // 0..3
    const int warpN = wid & 1;            // 0..1
    const int rowBase = blockIdx.y * 128;
    const int colBase = blockIdx.x * 128;

    float acc[2][8][4] = {};

    // ldmatrix lane-address components
    const int aRow = lane & 15;                       // A: row within 16
    const int aCol = (lane >> 4) << 3;                // A: k-offset 0/8
    const int bRow = (lane & 7) + (((lane >> 3) & 1) << 3);  // B: k-row within 16
    const int bCol = (lane >> 4) << 3;                // B: n-offset 0/8

    for (int kt = 0; kt < K; kt += 32) {
        __syncthreads();
        {   // stage A (128x32 bf16 hi+lo): 2 threads per row
            int row = tid >> 1, seg = tid & 1;
            size_t gb = (size_t)(rowBase + row) * K + kt + seg * 16;
            int sb = row * 56 + seg * 16;
            *(uint4*)&Ash[sb]     = *(const uint4*)&Ah[gb];
            *(uint4*)&Ash[sb + 8] = *(const uint4*)&Ah[gb + 8];
            *(uint4*)&Asl[sb]     = *(const uint4*)&Al[gb];
            *(uint4*)&Asl[sb + 8] = *(const uint4*)&Al[gb + 8];
        }
        {   // stage B (32x128 bf16 hi+lo): 8 threads per row
            int row = tid >> 3, seg = tid & 7;
            size_t gb = (size_t)(kt + row) * N + colBase + seg * 16;
            int sb = row * 136 + seg * 16;
            *(uint4*)&Bsh[sb]     = *(const uint4*)&Bh[gb];
            *(uint4*)&Bsh[sb + 8] = *(const uint4*)&Bh[gb + 8];
            *(uint4*)&Bsl[sb]     = *(const uint4*)&Bl[gb];
            *(uint4*)&Bsl[sb + 8] = *(const uint4*)&Bl[gb + 8];
        }
        __syncthreads();

#pragma unroll
        for (int ks = 0; ks < 2; ++ks) {
            const int k0 = ks * 16;
            unsigned ah[2][4], al[2][4];
#pragma unroll
            for (int mt = 0; mt < 2; ++mt) {
                int r = warpM * 32 + mt * 16 + aRow;
                ldsm4(ah[mt], saddr(&Ash[r * 56 + k0 + aCol]));
                ldsm4(al[mt], saddr(&Asl[r * 56 + k0 + aCol]));
            }
#pragma unroll
            for (int ntp = 0; ntp < 4; ++ntp) {
                int n0 = warpN * 64 + ntp * 16;
                unsigned bh[4], bl[4];
                ldsm4t(bh, saddr(&Bsh[(k0 + bRow) * 136 + n0 + bCol]));
                ldsm4t(bl, saddr(&Bsl[(k0 + bRow) * 136 + n0 + bCol]));
#pragma unroll
                for (int mt = 0; mt < 2; ++mt) {
                    mma_bf16(acc[mt][2 * ntp],     ah[mt], bh);
                    mma_bf16(acc[mt][2 * ntp],     al[mt], bh);
                    mma_bf16(acc[mt][2 * ntp],     ah[mt], bl);
                    mma_bf16(acc[mt][2 * ntp + 1], ah[mt], bh + 2);
                    mma_bf16(acc[mt][2 * ntp + 1], al[mt], bh + 2);
                    mma_bf16(acc[mt][2 * ntp + 1], ah[mt], bl + 2);
                }
            }
        }
    }

#pragma unroll
    for (int mt = 0; mt < 2; ++mt) {
        int row = rowBase + warpM * 32 + mt * 16 + g;
#pragma unroll
        for (int nt = 0; nt < 8; ++nt) {
            int col = colBase + warpN * 64 + nt * 8 + 2 * q4;
            *(float2*)&C[(size_t)row * N + col] =
                make_float2(acc[mt][nt][0], acc[mt][nt][1]);
            *(float2*)&C[(size_t)(row + 8) * N + col] =
                make_float2(acc[mt][nt][2], acc[mt][nt][3]);
        }
    }
}

// ============================================================
// RoPE in place on q [MROWS, NH*HD] and k [MROWS, KVH*HD].
// ============================================================
__global__ void rope_kernel(float* __restrict__ q, float* __restrict__ k)
{
    const int QP = MROWS * NH * (HD / 2);
    const int KP = MROWS * KVH * (HD / 2);
    int idx = blockIdx.x * blockDim.x + threadIdx.x;
    if (idx >= QP + KP) return;

    float* buf;
    int row, head, j, rowdim;
    if (idx < QP) {
        int t = idx;
        j = t & 31; t >>= 5;
        head = t & (NH - 1); t >>= 5;
        row = t;
        buf = q; rowdim = NH * HD;
    } else {
        int t = idx - QP;
        j = t & 31; t >>= 5;
        head = t & (KVH - 1); t >>= 3;
        row = t;
        buf = k; rowdim = KVH * HD;
    }
    int pos = row & (SEQ - 1);
    float inv_freq = exp2f(-(float)j * 0.41524101186092029f);
    float ang = (float)pos * inv_freq;
    float c, s;
    sincosf(ang, &s, &c);

    float* p = buf + (size_t)row * rowdim + head * HD + j;
    float x1 = p[0], x2 = p[32];
    p[0]  = x1 * c - x2 * s;
    p[32] = x2 * c + x1 * s;
}

// ============================================================
// Flash attention, bf16x3 MMA + ldmatrix. Non-causal, GQA.
// Grid: (SEQ/128, NH, BATCH). 256 thr = 8 warps, warp owns 16 q rows.
// Dyn smem (bf16, stride 72): QP hi/lo [128][72] (Q staging then P),
// K hi/lo [64][72] ([key][d]), V hi/lo [64][72] ([key][d]) = 73728 B.
// Emits pre-split bf16 att (hi/lo) for the wo GEMM.
// ============================================================
__global__ void __launch_bounds__(256)
attn_kernel(const float* __restrict__ q,
            const ushortT* __restrict__ kh, const ushortT* __restrict__ kl,
            const ushortT* __restrict__ vh, const ushortT* __restrict__ vl,
            ushortT* __restrict__ atth, ushortT* __restrict__ attl)
{
    extern __shared__ ushortT smb[];
    ushortT* QPh = smb;                    // [128][72]
    ushortT* QPl = QPh + 128 * 72;
    ushortT* Kh  = QPl + 128 * 72;         // [64][72]
    ushortT* Kl  = Kh + 64 * 72;
    ushortT* Vh  = Kl + 64 * 72;           // [64][72]
    ushortT* Vl  = Vh + 64 * 72;

    const int tid  = threadIdx.x;
    const int lane = tid & 31;
    const int wid  = tid >> 5;
    const int g    = lane >> 2;
    const int q4   = lane & 3;
    const int qb   = blockIdx.x * 128;
    const int h    = blockIdx.y;
    const int b    = blockIdx.z;
    const int kvh  = h >> 2;
    const int m0w  = wid * 16;

    const float*   qg  = q  + (size_t)b * SEQ * HID + (size_t)h * HD;
    const ushortT* kgh = kh + (size_t)b * SEQ * KVDIM + (size_t)kvh * HD;
    const ushortT* kgl = kl + (size_t)b * SEQ * KVDIM + (size_t)kvh * HD;
    const ushortT* vgh = vh + (size_t)b * SEQ * KVDIM + (size_t)kvh * HD;
    const ushortT* vgl = vl + (size_t)b * SEQ * KVDIM + (size_t)kvh * HD;
    ushortT* oh = atth + (size_t)b * SEQ * HID + (size_t)h * HD;
    ushortT* ol = attl + (size_t)b * SEQ * HID + (size_t)h * HD;

    // stage Q (128x64), fold 1/8 scale, split to bf16 hi/lo
#pragma unroll
    for (int p = 0; p < 8; ++p) {
        int id = tid + p * 256;
        int m = id >> 4, d4 = (id & 15) * 4;
        float4 vq = *(const float4*)&qg[(size_t)(qb + m) * HID + d4];
        unsigned h0, l0, h1, l1;
        split2(vq.x * 0.125f, vq.y * 0.125f, h0, l0);
        split2(vq.z * 0.125f, vq.w * 0.125f, h1, l1);
        *(uint2*)&QPh[m * 72 + d4] = make_uint2(h0, h1);
        *(uint2*)&QPl[m * 72 + d4] = make_uint2(l0, l1);
    }
    __syncthreads();

    // ldmatrix lane-address components
    const int aRow = lane & 15;
    const int aCol = (lane >> 4) << 3;
    const int kRow = (lane & 7) + ((lane >> 4) << 3);        // K (non-trans): n-row
    const int kCol = ((lane >> 3) & 1) << 3;                 // K: k-offset 0/8
    const int vRow = (lane & 7) + (((lane >> 3) & 1) << 3);  // V (trans): k-row
    const int vCol = (lane >> 4) << 3;                       // V: n-offset 0/8

    // hoist Q fragments (hi/lo) into registers, once
    unsigned Qh[4][4], Ql[4][4];
#pragma unroll
    for (int kt = 0; kt < 4; ++kt) {
        ldsm4(Qh[kt], saddr(&QPh[(m0w + aRow) * 72 + kt * 16 + aCol]));
        ldsm4(Ql[kt], saddr(&QPl[(m0w + aRow) * 72 + kt * 16 + aCol]));
    }

    float Oa[8][4] = {};
    float miA = -3.0e38f, miB = -3.0e38f, liA = 0.0f, liB = 0.0f;

    for (int kb = 0; kb < SEQ; kb += 64) {
        __syncthreads();
        {   // stage pre-split K and V tiles (64x64 bf16 each, pure copies)
            int row = tid >> 2, seg = tid & 3;
            size_t gb = (size_t)(kb + row) * KVDIM + seg * 16;
            int sb = row * 72 + seg * 16;
            *(uint4*)&Kh[sb]     = *(const uint4*)&kgh[gb];
            *(uint4*)&Kh[sb + 8] = *(const uint4*)&kgh[gb + 8];
            *(uint4*)&Kl[sb]     = *(const uint4*)&kgl[gb];
            *(uint4*)&Kl[sb + 8] = *(const uint4*)&kgl[gb + 8];
            *(uint4*)&Vh[sb]     = *(const uint4*)&vgh[gb];
            *(uint4*)&Vh[sb + 8] = *(const uint4*)&vgh[gb + 8];
            *(uint4*)&Vl[sb]     = *(const uint4*)&vgl[gb];
            *(uint4*)&Vl[sb + 8] = *(const uint4*)&vgl[gb + 8];
        }
        __syncthreads();

        // ---- S = Q @ K^T ----
        float S[8][4] = {};
#pragma unroll
        for (int kt = 0; kt < 4; ++kt) {
            int k0 = kt * 16;
#pragma unroll
            for (int ntp = 0; ntp < 4; ++ntp) {
                int n0 = ntp * 16;
                unsigned bh[4], bl[4];
                ldsm4(bh, saddr(&Kh[(n0 + kRow) * 72 + k0 + kCol]));
                ldsm4(bl, saddr(&Kl[(n0 + kRow) * 72 + k0 + kCol]));
                mma_bf16(S[2 * ntp],     Qh[kt], bh);
                mma_bf16(S[2 * ntp],     Ql[kt], bh);
                mma_bf16(S[2 * ntp],     Qh[kt], bl);
                mma_bf16(S[2 * ntp + 1], Qh[kt], bh + 2);
                mma_bf16(S[2 * ntp + 1], Ql[kt], bh + 2);
                mma_bf16(S[2 * ntp + 1], Qh[kt], bl + 2);
            }
        }

        // ---- online softmax (rows m0w+g, m0w+8+g) ----
        float mA = -3.0e38f, mB = -3.0e38f;
#pragma unroll
        for (int nt = 0; nt < 8; ++nt) {
            mA = fmaxf(mA, fmaxf(S[nt][0], S[nt][1]));
            mB = fmaxf(mB, fmaxf(S[nt][2], S[nt][3]));
        }
        mA = fmaxf(mA, __shfl_xor_sync(0xffffffffu, mA, 1));
        mA = fmaxf(mA, __shfl_xor_sync(0xffffffffu, mA, 2));
        mB = fmaxf(mB, __shfl_xor_sync(0xffffffffu, mB, 1));
        mB = fmaxf(mB, __shfl_xor_sync(0xffffffffu, mB, 2));

        float mnA = fmaxf(miA, mA), mnB = fmaxf(miB, mB);
        float aA = __expf(miA - mnA), aB = __expf(miB - mnB);
        miA = mnA; miB = mnB;

        float sA = 0.0f, sB = 0.0f;
#pragma unroll
        for (int nt = 0; nt < 8; ++nt) {
            S[nt][0] = __expf(S[nt][0] - mnA);
            S[nt][1] = __expf(S[nt][1] - mnA);
            S[nt][2] = __expf(S[nt][2] - mnB);
            S[nt][3] = __expf(S[nt][3] - mnB);
            sA += S[nt][0] + S[nt][1];
            sB += S[nt][2] + S[nt][3];
        }
        sA += __shfl_xor_sync(0xffffffffu, sA, 1);
        sA += __shfl_xor_sync(0xffffffffu, sA, 2);
        sB += __shfl_xor_sync(0xffffffffu, sB, 1);
        sB += __shfl_xor_sync(0xffffffffu, sB, 2);
        liA = liA * aA + sA;
        liB = liB * aB + sB;

        // rescale O, store P (bf16 hi/lo) into warp-private QP rows
#pragma unroll
        for (int nt = 0; nt < 8; ++nt) {
            Oa[nt][0] *= aA; Oa[nt][1] *= aA;
            Oa[nt][2] *= aB; Oa[nt][3] *= aB;
            int col = nt * 8 + 2 * q4;
            unsigned hp, lp;
            split2(S[nt][0], S[nt][1], hp, lp);
            *(unsigned*)&QPh[(m0w + g) * 72 + col] = hp;
            *(unsigned*)&QPl[(m0w + g) * 72 + col] = lp;
            split2(S[nt][2], S[nt][3], hp, lp);
            *(unsigned*)&QPh[(m0w + 8 + g) * 72 + col] = hp;
            *(unsigned*)&QPl[(m0w + 8 + g) * 72 + col] = lp;
        }
        __syncwarp();

        // ---- O += P @ V ----
#pragma unroll
        for (int kt = 0; kt < 4; ++kt) {
            int k0 = kt * 16;
            unsigned ph[4], pl[4];
            ldsm4(ph, saddr(&QPh[(m0w + aRow) * 72 + k0 + aCol]));
            ldsm4(pl, saddr(&QPl[(m0w + aRow) * 72 + k0 + aCol]));
#pragma unroll
            for (int ntp = 0; ntp < 4; ++ntp) {
                int n0 = ntp * 16;
                unsigned bh[4], bl[4];
                ldsm4t(bh, saddr(&Vh[(k0 + vRow) * 72 + n0 + vCol]));
                ldsm4t(bl, saddr(&Vl[(k0 + vRow) * 72 + n0 + vCol]));
                mma_bf16(Oa[2 * ntp],     ph, bh);
                mma_bf16(Oa[2 * ntp],     pl, bh);
                mma_bf16(Oa[2 * ntp],     ph, bl);
                mma_bf16(Oa[2 * ntp + 1], ph, bh + 2);
                mma_bf16(Oa[2 * ntp + 1], pl, bh + 2);
                mma_bf16(Oa[2 * ntp + 1], ph, bl + 2);
            }
        }
    }

    // epilogue: normalize, split to bf16 hi/lo, store
    float invA = 1.0f / liA, invB = 1.0f / liB;
#pragma unroll
    for (int nt = 0; nt < 8; ++nt) {
        int col = nt * 8 + 2 * q4;
        size_t rA = (size_t)(qb + m0w + g) * HID + col;
        size_t rB = (size_t)(qb + m0w + 8 + g) * HID + col;
        unsigned hp, lp;
        split2(Oa[nt][0] * invA, Oa[nt][1] * invA, hp, lp);
        *(unsigned*)&oh[rA] = hp;
        *(unsigned*)&ol[rA] = lp;
        split2(Oa[nt][2] * invB, Oa[nt][3] * invB, hp, lp);
        *(unsigned*)&oh[rB] = hp;
        *(unsigned*)&ol[rB] = lp;
    }
}

// ============================================================
// launch
// ============================================================
extern "C" void kernel_launch(void* const* d_in, const int* in_sizes, int n_in,
                              void* d_out, int out_size)
{
    const float* x  = (const float*)d_in[0];
    const float* wq = (const float*)d_in[1];
    const float* wk = (const float*)d_in[2];
    const float* wv = (const float*)d_in[3];
    const float* wo = (const float*)d_in[4];
    float* out = (float*)d_out;

    float *qp, *kp, *vp;
    ushortT *xh, *xl, *wqh, *wql, *wkh, *wkl, *wvh, *wvl, *woh, *wol;
    ushortT *khp, *klp, *vhp, *vlp, *ath, *atl;
    cudaGetSymbolAddress((void**)&qp, g_q);
    cudaGetSymbolAddress((void**)&kp, g_k);
    cudaGetSymbolAddress((void**)&vp, g_v);
    cudaGetSymbolAddress((void**)&xh, g_xh);   cudaGetSymbolAddress((void**)&xl, g_xl);
    cudaGetSymbolAddress((void**)&wqh, g_wqh); cudaGetSymbolAddress((void**)&wql, g_wql);
    cudaGetSymbolAddress((void**)&wkh, g_wkh); cudaGetSymbolAddress((void**)&wkl, g_wkl);
    cudaGetSymbolAddress((void**)&wvh, g_wvh); cudaGetSymbolAddress((void**)&wvl, g_wvl);
    cudaGetSymbolAddress((void**)&woh, g_woh); cudaGetSymbolAddress((void**)&wol, g_wol);
    cudaGetSymbolAddress((void**)&khp, g_kh);  cudaGetSymbolAddress((void**)&klp, g_kl);
    cudaGetSymbolAddress((void**)&vhp, g_vh);  cudaGetSymbolAddress((void**)&vlp, g_vl);
    cudaGetSymbolAddress((void**)&ath, g_atth);cudaGetSymbolAddress((void**)&atl, g_attl);

    dim3 blk(256);

    // pre-split inputs + weights into bf16 hi/lo (same bytes as fp32)
    split_bf16_kernel<<<(MROWS * HID) / 1024, 256>>>(x, xh, xl, MROWS * HID);
    split_bf16_kernel<<<(HID * HID) / 1024, 256>>>(wq, wqh, wql, HID * HID);
    split_bf16_kernel<<<(HID * KVDIM) / 1024, 256>>>(wk, wkh, wkl, HID * KVDIM);
    split_bf16_kernel<<<(HID * KVDIM) / 1024, 256>>>(wv, wvh, wvl, HID * KVDIM);
    split_bf16_kernel<<<(HID * HID) / 1024, 256>>>(wo, woh, wol, HID * HID);

    // QKV projections (fp32 outputs)
    gemm_bf16_kernel<<<dim3(HID / 128, MROWS / 128), blk>>>(xh, xl, wqh, wql, qp, MROWS, HID, HID);
    gemm_bf16_kernel<<<dim3(KVDIM / 128, MROWS / 128), blk>>>(xh, xl, wkh, wkl, kp, MROWS, KVDIM, HID);
    gemm_bf16_kernel<<<dim3(KVDIM / 128, MROWS / 128), blk>>>(xh, xl, wvh, wvl, vp, MROWS, KVDIM, HID);

    // RoPE on q, k (fp32)
    int total = MROWS * NH * (HD / 2) + MROWS * KVH * (HD / 2);
    rope_kernel<<<(total + 255) / 256, 256>>>(qp, kp);

    // split roped k and v
    split_bf16_kernel<<<(MROWS * KVDIM) / 1024, 256>>>(kp, khp, klp, MROWS * KVDIM);
    split_bf16_kernel<<<(MROWS * KVDIM) / 1024, 256>>>(vp, vhp, vlp, MROWS * KVDIM);

    // attention (emits pre-split bf16 att)
    cudaFuncSetAttribute(attn_kernel, cudaFuncAttributeMaxDynamicSharedMemorySize, 73728);
    attn_kernel<<<dim3(SEQ / 128, NH, BATCH), blk, 73728>>>(qp, khp, klp, vhp, vlp, ath, atl);

    // output projection -> fp32 d_out
    gemm_bf16_kernel<<<dim3(HID / 128, MROWS / 128), blk>>>(ath, atl, woh, wol, out, MROWS, HID, HID);
}

// round 14
// speedup vs baseline: 2.9040x; 1.5401x over previous
#include <cuda_runtime.h>
#include <cuda_fp16.h>
#include <cuda_bf16.h>
#include <math.h>

// ---- problem constants ----
#define HID    2048
#define NH     32
#define KVH    8
#define HD     64
#define BATCH  2
#define SEQ    2048
#define MROWS  (BATCH * SEQ)   // 4096
#define KVDIM  (KVH * HD)      // 512

typedef unsigned short ushortT;

// ---- scratch (device globals: allocation-free) ----
__device__ float   g_q[(size_t)MROWS * HID];
__device__ float   g_k[(size_t)MROWS * KVDIM];
__device__ float   g_v[(size_t)MROWS * KVDIM];

// fp16 operands for projection GEMMs
__device__ ushortT g_xh[(size_t)MROWS * HID], g_xl[(size_t)MROWS * HID];
__device__ ushortT g_wqh[(size_t)HID * HID];          // [K,N] fp16 hi only
__device__ ushortT g_wkh[(size_t)HID * KVDIM];
__device__ ushortT g_wvh[(size_t)HID * KVDIM];
__device__ ushortT g_woh[(size_t)HID * HID];
__device__ ushortT g_atth[(size_t)MROWS * HID], g_attl[(size_t)MROWS * HID]; // fp16 hi/lo

// bf16 operands for attention (unchanged path)
__device__ ushortT g_kh[(size_t)MROWS * KVDIM], g_kl[(size_t)MROWS * KVDIM];
__device__ ushortT g_vh[(size_t)MROWS * KVDIM], g_vl[(size_t)MROWS * KVDIM];

// ---- generic helpers ----
__device__ __forceinline__ unsigned saddr(const void* p) {
    return (unsigned)__cvta_generic_to_shared(p);
}
__device__ __forceinline__ void ldsm4(unsigned* r, unsigned a) {
    asm volatile("ldmatrix.sync.aligned.m8n8.x4.shared.b16 {%0,%1,%2,%3}, [%4];"
                 : "=r"(r[0]), "=r"(r[1]), "=r"(r[2]), "=r"(r[3]) : "r"(a));
}
__device__ __forceinline__ void ldsm4t(unsigned* r, unsigned a) {
    asm volatile("ldmatrix.sync.aligned.m8n8.x4.trans.shared.b16 {%0,%1,%2,%3}, [%4];"
                 : "=r"(r[0]), "=r"(r[1]), "=r"(r[2]), "=r"(r[3]) : "r"(a));
}
__device__ __forceinline__ void mma_bf16(float* c, const unsigned* a, const unsigned* b) {
    asm volatile(
        "mma.sync.aligned.m16n8k16.row.col.f32.bf16.bf16.f32 "
        "{%0,%1,%2,%3}, {%4,%5,%6,%7}, {%8,%9}, {%0,%1,%2,%3};"
        : "+f"(c[0]), "+f"(c[1]), "+f"(c[2]), "+f"(c[3])
        : "r"(a[0]), "r"(a[1]), "r"(a[2]), "r"(a[3]), "r"(b[0]), "r"(b[1]));
}
__device__ __forceinline__ void mma_f16(float* c, const unsigned* a, const unsigned* b) {
    asm volatile(
        "mma.sync.aligned.m16n8k16.row.col.f32.f16.f16.f32 "
        "{%0,%1,%2,%3}, {%4,%5,%6,%7}, {%8,%9}, {%0,%1,%2,%3};"
        : "+f"(c[0]), "+f"(c[1]), "+f"(c[2]), "+f"(c[3])
        : "r"(a[0]), "r"(a[1]), "r"(a[2]), "r"(a[3]), "r"(b[0]), "r"(b[1]));
}
// bf16 hi/lo split of two floats (attention path)
__device__ __forceinline__ void split2(float a, float b, unsigned& hp, unsigned& lp) {
    __nv_bfloat16 ha = __float2bfloat16_rn(a), hb = __float2bfloat16_rn(b);
    __nv_bfloat16 la = __float2bfloat16_rn(a - __bfloat162float(ha));
    __nv_bfloat16 lb = __float2bfloat16_rn(b - __bfloat162float(hb));
    __nv_bfloat162 hv(ha, hb), lv(la, lb);
    hp = *reinterpret_cast<unsigned*>(&hv);
    lp = *reinterpret_cast<unsigned*>(&lv);
}
// fp16 hi/lo split of two floats (projection path)
__device__ __forceinline__ void split2h(float a, float b, unsigned& hp, unsigned& lp) {
    __half ha = __float2half_rn(a), hb = __float2half_rn(b);
    __half la = __float2half_rn(a - __half2float(ha));
    __half lb = __float2half_rn(b - __half2float(hb));
    __half2 hv = __halves2half2(ha, hb), lv = __halves2half2(la, lb);
    hp = *reinterpret_cast<unsigned*>(&hv);
    lp = *reinterpret_cast<unsigned*>(&lv);
}
// cp.async 16B
__device__ __forceinline__ void cpa16(unsigned d, const void* s) {
    asm volatile("cp.async.cg.shared.global [%0], [%1], 16;" :: "r"(d), "l"(s) : "memory");
}
#define CP_COMMIT() asm volatile("cp.async.commit_group;" ::: "memory")
#define CP_WAIT1()  asm volatile("cp.async.wait_group 1;" ::: "memory")

// ============================================================
// split kernels
// ============================================================
__global__ void split_f16hl_kernel(const float* __restrict__ in,
                                   ushortT* __restrict__ hi, ushortT* __restrict__ lo,
                                   int n)
{
    int i = (blockIdx.x * blockDim.x + threadIdx.x) * 4;
    if (i >= n) return;
    float4 v = *(const float4*)&in[i];
    unsigned h0, l0, h1, l1;
    split2h(v.x, v.y, h0, l0);
    split2h(v.z, v.w, h1, l1);
    *(uint2*)&hi[i] = make_uint2(h0, h1);
    *(uint2*)&lo[i] = make_uint2(l0, l1);
}
__global__ void split_f16h_kernel(const float* __restrict__ in,
                                  ushortT* __restrict__ hi, int n)
{
    int i = (blockIdx.x * blockDim.x + threadIdx.x) * 4;
    if (i >= n) return;
    float4 v = *(const float4*)&in[i];
    __half2 a = __halves2half2(__float2half_rn(v.x), __float2half_rn(v.y));
    __half2 b = __halves2half2(__float2half_rn(v.z), __float2half_rn(v.w));
    *(uint2*)&hi[i] = make_uint2(*(unsigned*)&a, *(unsigned*)&b);
}
__global__ void split_bf16_kernel(const float* __restrict__ in,
                                  ushortT* __restrict__ hi, ushortT* __restrict__ lo,
                                  int n)
{
    int i = (blockIdx.x * blockDim.x + threadIdx.x) * 4;
    if (i >= n) return;
    float4 v = *(const float4*)&in[i];
    unsigned h0, l0, h1, l1;
    split2(v.x, v.y, h0, l0);
    split2(v.z, v.w, h1, l1);
    *(uint2*)&hi[i] = make_uint2(h0, h1);
    *(uint2*)&lo[i] = make_uint2(l0, l1);
}

// ============================================================
// fp16 2-term GEMM with cp.async double buffering + output routing.
// C_seg[M, n_seg](f32) = A[M,K] @ B_seg[K, n_seg] per column-tile segment.
// 128x128 tile, BK=32, 256 thr = 8 warps (4M x 2N).
// Per stage smem: Ah[128*56], Al[128*56], Bh[32*136] fp16 = 37376 B; x2 stages.
// ============================================================
#define ASZ (128 * 56)
#define BSZ (32 * 136)
#define STG (2 * ASZ + BSZ)

__device__ __forceinline__ void gemm_stage(
    ushortT* sb, const ushortT* __restrict__ Ah, const ushortT* __restrict__ Al,
    const ushortT* __restrict__ Bh, int rowBase, int colBase, int kt,
    int K, int Nb, int tid)
{
    unsigned sbu = saddr(sb);
#pragma unroll
    for (int rep = 0; rep < 2; ++rep) {
        int cid = tid + rep * 256;          // A chunk: 512 total
        int row = cid >> 2, seg = cid & 3;
        size_t ga = (size_t)(rowBase + row) * K + kt + seg * 8;
        unsigned d = sbu + (row * 56 + seg * 8) * 2;
        cpa16(d, &Ah[ga]);
        cpa16(d + ASZ * 2, &Al[ga]);
    }
#pragma unroll
    for (int rep = 0; rep < 2; ++rep) {
        int cid = tid + rep * 256;          // B chunk: 512 total
        int row = cid >> 4, seg = cid & 15;
        size_t gb = (size_t)(kt + row) * Nb + colBase + seg * 8;
        cpa16(sbu + (2 * ASZ + row * 136 + seg * 8) * 2, &Bh[gb]);
    }
}

__global__ void __launch_bounds__(256)
gemm_f16_kernel(const ushortT* __restrict__ Ah, const ushortT* __restrict__ Al,
                const ushortT* __restrict__ B0, const ushortT* __restrict__ B1,
                const ushortT* __restrict__ B2,
                float* __restrict__ C0, float* __restrict__ C1, float* __restrict__ C2,
                int t1, int t2, int n0, int n1, int n2, int K)
{
    extern __shared__ ushortT sm[];

    const int tid  = threadIdx.x;
    const int lane = tid & 31;
    const int wid  = tid >> 5;
    const int g    = lane >> 2;
    const int q4   = lane & 3;
    const int warpM = wid >> 1;
    const int warpN = wid & 1;
    const int rowBase = blockIdx.y * 128;

    // route column tile -> (B, C, N)
    int ct = blockIdx.x;
    const ushortT* Bh; float* C; int Nb; int ctl;
    if (ct < t1)      { Bh = B0; C = C0; Nb = n0; ctl = ct; }
    else if (ct < t2) { Bh = B1; C = C1; Nb = n1; ctl = ct - t1; }
    else              { Bh = B2; C = C2; Nb = n2; ctl = ct - t2; }
    const int colBase = ctl * 128;

    const int NIT = K >> 5;

    gemm_stage(sm,       Ah, Al, Bh, rowBase, colBase, 0,  K, Nb, tid);
    CP_COMMIT();
    gemm_stage(sm + STG, Ah, Al, Bh, rowBase, colBase, 32, K, Nb, tid);
    CP_COMMIT();

    float acc[2][8][4] = {};

    const int aRow = lane & 15;
    const int aCol = (lane >> 4) << 3;
    const int bRow = (lane & 7) + (((lane >> 3) & 1) << 3);
    const int bCol = (lane >> 4) << 3;

    for (int i = 0; i < NIT; ++i) {
        CP_WAIT1();
        __syncthreads();
        ushortT* sA  = sm + (i & 1) * STG;
        ushortT* sAl = sA + ASZ;
        ushortT* sB  = sA + 2 * ASZ;

#pragma unroll
        for (int ks = 0; ks < 2; ++ks) {
            const int k0 = ks * 16;
            unsigned ah[2][4], al[2][4];
#pragma unroll
            for (int mt = 0; mt < 2; ++mt) {
                int r = warpM * 32 + mt * 16 + aRow;
                ldsm4(ah[mt], saddr(&sA[r * 56 + k0 + aCol]));
                ldsm4(al[mt], saddr(&sAl[r * 56 + k0 + aCol]));
            }
#pragma unroll
            for (int ntp = 0; ntp < 4; ++ntp) {
                int n0b = warpN * 64 + ntp * 16;
                unsigned bh[4];
                ldsm4t(bh, saddr(&sB[(k0 + bRow) * 136 + n0b + bCol]));
#pragma unroll
                for (int mt = 0; mt < 2; ++mt) {
                    mma_f16(acc[mt][2 * ntp],     ah[mt], bh);
                    mma_f16(acc[mt][2 * ntp],     al[mt], bh);
                    mma_f16(acc[mt][2 * ntp + 1], ah[mt], bh + 2);
                    mma_f16(acc[mt][2 * ntp + 1], al[mt], bh + 2);
                }
            }
        }
        __syncthreads();
        if (i + 2 < NIT)
            gemm_stage(sm + (i & 1) * STG, Ah, Al, Bh,
                       rowBase, colBase, (i + 2) * 32, K, Nb, tid);
        CP_COMMIT();
    }

#pragma unroll
    for (int mt = 0; mt < 2; ++mt) {
        int row = rowBase + warpM * 32 + mt * 16 + g;
#pragma unroll
        for (int nt = 0; nt < 8; ++nt) {
            int col = colBase + warpN * 64 + nt * 8 + 2 * q4;
            *(float2*)&C[(size_t)row * Nb + col] =
                make_float2(acc[mt][nt][0], acc[mt][nt][1]);
            *(float2*)&C[(size_t)(row + 8) * Nb + col] =
                make_float2(acc[mt][nt][2], acc[mt][nt][3]);
        }
    }
}

// ============================================================
// RoPE in place on q [MROWS, NH*HD] and k [MROWS, KVH*HD].
// ============================================================
__global__ void rope_kernel(float* __restrict__ q, float* __restrict__ k)
{
    const int QP = MROWS * NH * (HD / 2);
    const int KP = MROWS * KVH * (HD / 2);
    int idx = blockIdx.x * blockDim.x + threadIdx.x;
    if (idx >= QP + KP) return;

    float* buf;
    int row, head, j, rowdim;
    if (idx < QP) {
        int t = idx;
        j = t & 31; t >>= 5;
        head = t & (NH - 1); t >>= 5;
        row = t;
        buf = q; rowdim = NH * HD;
    } else {
        int t = idx - QP;
        j = t & 31; t >>= 5;
        head = t & (KVH - 1); t >>= 3;
        row = t;
        buf = k; rowdim = KVH * HD;
    }
    int pos = row & (SEQ - 1);
    float inv_freq = exp2f(-(float)j * 0.41524101186092029f);
    float ang = (float)pos * inv_freq;
    float c, s;
    sincosf(ang, &s, &c);

    float* p = buf + (size_t)row * rowdim + head * HD + j;
    float x1 = p[0], x2 = p[32];
    p[0]  = x1 * c - x2 * s;
    p[32] = x2 * c + x1 * s;
}

// ============================================================
// Flash attention, bf16x3 MMA + ldmatrix (round-12 proven path).
// Only change: epilogue emits fp16 hi/lo att for the fp16 out-proj.
// ============================================================
__global__ void __launch_bounds__(256)
attn_kernel(const float* __restrict__ q,
            const ushortT* __restrict__ kh, const ushortT* __restrict__ kl,
            const ushortT* __restrict__ vh, const ushortT* __restrict__ vl,
            ushortT* __restrict__ atth, ushortT* __restrict__ attl)
{
    extern __shared__ ushortT smb[];
    ushortT* QPh = smb;                    // [128][72]
    ushortT* QPl = QPh + 128 * 72;
    ushortT* Kh  = QPl + 128 * 72;         // [64][72]
    ushortT* Kl  = Kh + 64 * 72;
    ushortT* Vh  = Kl + 64 * 72;           // [64][72]
    ushortT* Vl  = Vh + 64 * 72;

    const int tid  = threadIdx.x;
    const int lane = tid & 31;
    const int wid  = tid >> 5;
    const int g    = lane >> 2;
    const int q4   = lane & 3;
    const int qb   = blockIdx.x * 128;
    const int h    = blockIdx.y;
    const int b    = blockIdx.z;
    const int kvh  = h >> 2;
    const int m0w  = wid * 16;

    const float*   qg  = q  + (size_t)b * SEQ * HID + (size_t)h * HD;
    const ushortT* kgh = kh + (size_t)b * SEQ * KVDIM + (size_t)kvh * HD;
    const ushortT* kgl = kl + (size_t)b * SEQ * KVDIM + (size_t)kvh * HD;
    const ushortT* vgh = vh + (size_t)b * SEQ * KVDIM + (size_t)kvh * HD;
    const ushortT* vgl = vl + (size_t)b * SEQ * KVDIM + (size_t)kvh * HD;
    ushortT* oh = atth + (size_t)b * SEQ * HID + (size_t)h * HD;
    ushortT* ol = attl + (size_t)b * SEQ * HID + (size_t)h * HD;

#pragma unroll
    for (int p = 0; p < 8; ++p) {
        int id = tid + p * 256;
        int m = id >> 4, d4 = (id & 15) * 4;
        float4 vq = *(const float4*)&qg[(size_t)(qb + m) * HID + d4];
        unsigned h0, l0, h1, l1;
        split2(vq.x * 0.125f, vq.y * 0.125f, h0, l0);
        split2(vq.z * 0.125f, vq.w * 0.125f, h1, l1);
        *(uint2*)&QPh[m * 72 + d4] = make_uint2(h0, h1);
        *(uint2*)&QPl[m * 72 + d4] = make_uint2(l0, l1);
    }
    __syncthreads();

    const int aRow = lane & 15;
    const int aCol = (lane >> 4) << 3;
    const int kRow = (lane & 7) + ((lane >> 4) << 3);
    const int kCol = ((lane >> 3) & 1) << 3;
    const int vRow = (lane & 7) + (((lane >> 3) & 1) << 3);
    const int vCol = (lane >> 4) << 3;

    unsigned Qh[4][4], Ql[4][4];
#pragma unroll
    for (int kt = 0; kt < 4; ++kt) {
        ldsm4(Qh[kt], saddr(&QPh[(m0w + aRow) * 72 + kt * 16 + aCol]));
        ldsm4(Ql[kt], saddr(&QPl[(m0w + aRow) * 72 + kt * 16 + aCol]));
    }

    float Oa[8][4] = {};
    float miA = -3.0e38f, miB = -3.0e38f, liA = 0.0f, liB = 0.0f;

    for (int kb = 0; kb < SEQ; kb += 64) {
        __syncthreads();
        {
            int row = tid >> 2, seg = tid & 3;
            size_t gb = (size_t)(kb + row) * KVDIM + seg * 16;
            int sb = row * 72 + seg * 16;
            *(uint4*)&Kh[sb]     = *(const uint4*)&kgh[gb];
            *(uint4*)&Kh[sb + 8] = *(const uint4*)&kgh[gb + 8];
            *(uint4*)&Kl[sb]     = *(const uint4*)&kgl[gb];
            *(uint4*)&Kl[sb + 8] = *(const uint4*)&kgl[gb + 8];
            *(uint4*)&Vh[sb]     = *(const uint4*)&vgh[gb];
            *(uint4*)&Vh[sb + 8] = *(const uint4*)&vgh[gb + 8];
            *(uint4*)&Vl[sb]     = *(const uint4*)&vgl[gb];
            *(uint4*)&Vl[sb + 8] = *(const uint4*)&vgl[gb + 8];
        }
        __syncthreads();

        float S[8][4] = {};
#pragma unroll
        for (int kt = 0; kt < 4; ++kt) {
            int k0 = kt * 16;
#pragma unroll
            for (int ntp = 0; ntp < 4; ++ntp) {
                int n0 = ntp * 16;
                unsigned bh[4], bl[4];
                ldsm4(bh, saddr(&Kh[(n0 + kRow) * 72 + k0 + kCol]));
                ldsm4(bl, saddr(&Kl[(n0 + kRow) * 72 + k0 + kCol]));
                mma_bf16(S[2 * ntp],     Qh[kt], bh);
                mma_bf16(S[2 * ntp],     Ql[kt], bh);
                mma_bf16(S[2 * ntp],     Qh[kt], bl);
                mma_bf16(S[2 * ntp + 1], Qh[kt], bh + 2);
                mma_bf16(S[2 * ntp + 1], Ql[kt], bh + 2);
                mma_bf16(S[2 * ntp + 1], Qh[kt], bl + 2);
            }
        }

        float mA = -3.0e38f, mB = -3.0e38f;
#pragma unroll
        for (int nt = 0; nt < 8; ++nt) {
            mA = fmaxf(mA, fmaxf(S[nt][0], S[nt][1]));
            mB = fmaxf(mB, fmaxf(S[nt][2], S[nt][3]));
        }
        mA = fmaxf(mA, __shfl_xor_sync(0xffffffffu, mA, 1));
        mA = fmaxf(mA, __shfl_xor_sync(0xffffffffu, mA, 2));
        mB = fmaxf(mB, __shfl_xor_sync(0xffffffffu, mB, 1));
        mB = fmaxf(mB, __shfl_xor_sync(0xffffffffu, mB, 2));

        float mnA = fmaxf(miA, mA), mnB = fmaxf(miB, mB);
        float aA = __expf(miA - mnA), aB = __expf(miB - mnB);
        miA = mnA; miB = mnB;

        float sA = 0.0f, sB = 0.0f;
#pragma unroll
        for (int nt = 0; nt < 8; ++nt) {
            S[nt][0] = __expf(S[nt][0] - mnA);
            S[nt][1] = __expf(S[nt][1] - mnA);
            S[nt][2] = __expf(S[nt][2] - mnB);
            S[nt][3] = __expf(S[nt][3] - mnB);
            sA += S[nt][0] + S[nt][1];
            sB += S[nt][2] + S[nt][3];
        }
        sA += __shfl_xor_sync(0xffffffffu, sA, 1);
        sA += __shfl_xor_sync(0xffffffffu, sA, 2);
        sB += __shfl_xor_sync(0xffffffffu, sB, 1);
        sB += __shfl_xor_sync(0xffffffffu, sB, 2);
        liA = liA * aA + sA;
        liB = liB * aB + sB;

#pragma unroll
        for (int nt = 0; nt < 8; ++nt) {
            Oa[nt][0] *= aA; Oa[nt][1] *= aA;
            Oa[nt][2] *= aB; Oa[nt][3] *= aB;
            int col = nt * 8 + 2 * q4;
            unsigned hp, lp;
            split2(S[nt][0], S[nt][1], hp, lp);
            *(unsigned*)&QPh[(m0w + g) * 72 + col] = hp;
            *(unsigned*)&QPl[(m0w + g) * 72 + col] = lp;
            split2(S[nt][2], S[nt][3], hp, lp);
            *(unsigned*)&QPh[(m0w + 8 + g) * 72 + col] = hp;
            *(unsigned*)&QPl[(m0w + 8 + g) * 72 + col] = lp;
        }
        __syncwarp();

#pragma unroll
        for (int kt = 0; kt < 4; ++kt) {
            int k0 = kt * 16;
            unsigned ph[4], pl[4];
            ldsm4(ph, saddr(&QPh[(m0w + aRow) * 72 + k0 + aCol]));
            ldsm4(pl, saddr(&QPl[(m0w + aRow) * 72 + k0 + aCol]));
#pragma unroll
            for (int ntp = 0; ntp < 4; ++ntp) {
                int n0 = ntp * 16;
                unsigned bh[4], bl[4];
                ldsm4t(bh, saddr(&Vh[(k0 + vRow) * 72 + n0 + vCol]));
                ldsm4t(bl, saddr(&Vl[(k0 + vRow) * 72 + n0 + vCol]));
                mma_bf16(Oa[2 * ntp],     ph, bh);
                mma_bf16(Oa[2 * ntp],     pl, bh);
                mma_bf16(Oa[2 * ntp],     ph, bl);
                mma_bf16(Oa[2 * ntp + 1], ph, bh + 2);
                mma_bf16(Oa[2 * ntp + 1], pl, bh + 2);
                mma_bf16(Oa[2 * ntp + 1], ph, bl + 2);
            }
        }
    }

    // epilogue: normalize, split to fp16 hi/lo (for fp16 out-projection)
    float invA = 1.0f / liA, invB = 1.0f / liB;
#pragma unroll
    for (int nt = 0; nt < 8; ++nt) {
        int col = nt * 8 + 2 * q4;
        size_t rA = (size_t)(qb + m0w + g) * HID + col;
        size_t rB = (size_t)(qb + m0w + 8 + g) * HID + col;
        unsigned hp, lp;
        split2h(Oa[nt][0] * invA, Oa[nt][1] * invA, hp, lp);
        *(unsigned*)&oh[rA] = hp;
        *(unsigned*)&ol[rA] = lp;
        split2h(Oa[nt][2] * invB, Oa[nt][3] * invB, hp, lp);
        *(unsigned*)&oh[rB] = hp;
        *(unsigned*)&ol[rB] = lp;
    }
}

// ============================================================
// launch
// ============================================================
extern "C" void kernel_launch(void* const* d_in, const int* in_sizes, int n_in,
                              void* d_out, int out_size)
{
    const float* x  = (const float*)d_in[0];
    const float* wq = (const float*)d_in[1];
    const float* wk = (const float*)d_in[2];
    const float* wv = (const float*)d_in[3];
    const float* wo = (const float*)d_in[4];
    float* out = (float*)d_out;

    float *qp, *kp, *vp;
    ushortT *xh, *xl, *wqh, *wkh, *wvh, *woh;
    ushortT *khp, *klp, *vhp, *vlp, *ath, *atl;
    cudaGetSymbolAddress((void**)&qp, g_q);
    cudaGetSymbolAddress((void**)&kp, g_k);
    cudaGetSymbolAddress((void**)&vp, g_v);
    cudaGetSymbolAddress((void**)&xh, g_xh);   cudaGetSymbolAddress((void**)&xl, g_xl);
    cudaGetSymbolAddress((void**)&wqh, g_wqh);
    cudaGetSymbolAddress((void**)&wkh, g_wkh);
    cudaGetSymbolAddress((void**)&wvh, g_wvh);
    cudaGetSymbolAddress((void**)&woh, g_woh);
    cudaGetSymbolAddress((void**)&khp, g_kh);  cudaGetSymbolAddress((void**)&klp, g_kl);
    cudaGetSymbolAddress((void**)&vhp, g_vh);  cudaGetSymbolAddress((void**)&vlp, g_vl);
    cudaGetSymbolAddress((void**)&ath, g_atth);cudaGetSymbolAddress((void**)&atl, g_attl);

    dim3 blk(256);
    const int GEMM_SMEM = 2 * STG * 2;   // 2 stages x STG elems x 2 bytes = 74752

    // prep: x -> fp16 hi/lo; weights -> fp16 hi only ([K,N] layout unchanged)
    split_f16hl_kernel<<<(MROWS * HID) / 1024, 256>>>(x, xh, xl, MROWS * HID);
    split_f16h_kernel<<<(HID * HID) / 1024, 256>>>(wq, wqh, HID * HID);
    split_f16h_kernel<<<(HID * KVDIM) / 1024, 256>>>(wk, wkh, HID * KVDIM);
    split_f16h_kernel<<<(HID * KVDIM) / 1024, 256>>>(wv, wvh, HID * KVDIM);
    split_f16h_kernel<<<(HID * HID) / 1024, 256>>>(wo, woh, HID * HID);

    cudaFuncSetAttribute(gemm_f16_kernel, cudaFuncAttributeMaxDynamicSharedMemorySize, GEMM_SMEM);

    // merged QKV projection: 24 col tiles -> [0,16)=Q, [16,20)=K, [20,24)=V
    gemm_f16_kernel<<<dim3(24, MROWS / 128), blk, GEMM_SMEM>>>(
        xh, xl, wqh, wkh, wvh, qp, kp, vp,
        16, 20, HID, KVDIM, KVDIM, HID);

    // RoPE on q, k (fp32)
    int total = MROWS * NH * (HD / 2) + MROWS * KVH * (HD / 2);
    rope_kernel<<<(total + 255) / 256, 256>>>(qp, kp);

    // split roped k and v for attention (bf16 hi/lo, unchanged)
    split_bf16_kernel<<<(MROWS * KVDIM) / 1024, 256>>>(kp, khp, klp, MROWS * KVDIM);
    split_bf16_kernel<<<(MROWS * KVDIM) / 1024, 256>>>(vp, vhp, vlp, MROWS * KVDIM);

    // attention (emits fp16 hi/lo att)
    cudaFuncSetAttribute(attn_kernel, cudaFuncAttributeMaxDynamicSharedMemorySize, 73728);
    attn_kernel<<<dim3(SEQ / 128, NH, BATCH), blk, 73728>>>(qp, khp, klp, vhp, vlp, ath, atl);

    // output projection -> fp32 d_out (single segment)
    gemm_f16_kernel<<<dim3(16, MROWS / 128), blk, GEMM_SMEM>>>(
        ath, atl, woh, woh, woh, out, out, out,
        16, 32, HID, HID, HID, HID);
}

// round 15
// speedup vs baseline: 3.5437x; 1.2203x over previous
#include <cuda_runtime.h>
#include <cuda_fp16.h>
#include <math.h>

// ---- problem constants ----
#define HID    2048
#define NH     32
#define KVH    8
#define HD     64
#define BATCH  2
#define SEQ    2048
#define MROWS  (BATCH * SEQ)   // 4096
#define KVDIM  (KVH * HD)      // 512

typedef unsigned short ushortT;

// ---- scratch (device globals: allocation-free) ----
__device__ float   g_q[(size_t)MROWS * HID];
__device__ float   g_k[(size_t)MROWS * KVDIM];
__device__ float   g_v[(size_t)MROWS * KVDIM];

// fp16 operands
__device__ ushortT g_xh[(size_t)MROWS * HID], g_xl[(size_t)MROWS * HID];
__device__ ushortT g_wqh[(size_t)HID * HID];          // [K,N] fp16 hi only
__device__ ushortT g_wkh[(size_t)HID * KVDIM];
__device__ ushortT g_wvh[(size_t)HID * KVDIM];
__device__ ushortT g_woh[(size_t)HID * HID];
__device__ ushortT g_atth[(size_t)MROWS * HID], g_attl[(size_t)MROWS * HID];
__device__ ushortT g_kh[(size_t)MROWS * KVDIM];       // roped K, fp16 hi only
__device__ ushortT g_vh[(size_t)MROWS * KVDIM];       // V, fp16 hi only

// ---- generic helpers ----
__device__ __forceinline__ unsigned saddr(const void* p) {
    return (unsigned)__cvta_generic_to_shared(p);
}
__device__ __forceinline__ void ldsm4(unsigned* r, unsigned a) {
    asm volatile("ldmatrix.sync.aligned.m8n8.x4.shared.b16 {%0,%1,%2,%3}, [%4];"
                 : "=r"(r[0]), "=r"(r[1]), "=r"(r[2]), "=r"(r[3]) : "r"(a));
}
__device__ __forceinline__ void ldsm4t(unsigned* r, unsigned a) {
    asm volatile("ldmatrix.sync.aligned.m8n8.x4.trans.shared.b16 {%0,%1,%2,%3}, [%4];"
                 : "=r"(r[0]), "=r"(r[1]), "=r"(r[2]), "=r"(r[3]) : "r"(a));
}
__device__ __forceinline__ void mma_f16(float* c, const unsigned* a, const unsigned* b) {
    asm volatile(
        "mma.sync.aligned.m16n8k16.row.col.f32.f16.f16.f32 "
        "{%0,%1,%2,%3}, {%4,%5,%6,%7}, {%8,%9}, {%0,%1,%2,%3};"
        : "+f"(c[0]), "+f"(c[1]), "+f"(c[2]), "+f"(c[3])
        : "r"(a[0]), "r"(a[1]), "r"(a[2]), "r"(a[3]), "r"(b[0]), "r"(b[1]));
}
// fp16 hi/lo split of two floats
__device__ __forceinline__ void split2h(float a, float b, unsigned& hp, unsigned& lp) {
    __half ha = __float2half_rn(a), hb = __float2half_rn(b);
    __half la = __float2half_rn(a - __half2float(ha));
    __half lb = __float2half_rn(b - __half2float(hb));
    __half2 hv = __halves2half2(ha, hb), lv = __halves2half2(la, lb);
    hp = *reinterpret_cast<unsigned*>(&hv);
    lp = *reinterpret_cast<unsigned*>(&lv);
}
// cp.async 16B
__device__ __forceinline__ void cpa16(unsigned d, const void* s) {
    asm volatile("cp.async.cg.shared.global [%0], [%1], 16;" :: "r"(d), "l"(s) : "memory");
}
#define CP_COMMIT() asm volatile("cp.async.commit_group;" ::: "memory")
#define CP_WAIT1()  asm volatile("cp.async.wait_group 1;" ::: "memory")
#define CP_WAIT0()  asm volatile("cp.async.wait_group 0;" ::: "memory")

// ============================================================
// split kernels
// ============================================================
__global__ void split_f16hl_kernel(const float* __restrict__ in,
                                   ushortT* __restrict__ hi, ushortT* __restrict__ lo,
                                   int n)
{
    int i = (blockIdx.x * blockDim.x + threadIdx.x) * 4;
    if (i >= n) return;
    float4 v = *(const float4*)&in[i];
    unsigned h0, l0, h1, l1;
    split2h(v.x, v.y, h0, l0);
    split2h(v.z, v.w, h1, l1);
    *(uint2*)&hi[i] = make_uint2(h0, h1);
    *(uint2*)&lo[i] = make_uint2(l0, l1);
}
__global__ void split_f16h_kernel(const float* __restrict__ in,
                                  ushortT* __restrict__ hi, int n)
{
    int i = (blockIdx.x * blockDim.x + threadIdx.x) * 4;
    if (i >= n) return;
    float4 v = *(const float4*)&in[i];
    __half2 a = __halves2half2(__float2half_rn(v.x), __float2half_rn(v.y));
    __half2 b = __halves2half2(__float2half_rn(v.z), __float2half_rn(v.w));
    *(uint2*)&hi[i] = make_uint2(*(unsigned*)&a, *(unsigned*)&b);
}

// ============================================================
// fp16 2-term GEMM with cp.async double buffering + output routing.
// (unchanged from round 14 — passing at 3.8e-4 combined)
// ============================================================
#define ASZ (128 * 56)
#define BSZ (32 * 136)
#define STG (2 * ASZ + BSZ)

__device__ __forceinline__ void gemm_stage(
    ushortT* sb, const ushortT* __restrict__ Ah, const ushortT* __restrict__ Al,
    const ushortT* __restrict__ Bh, int rowBase, int colBase, int kt,
    int K, int Nb, int tid)
{
    unsigned sbu = saddr(sb);
#pragma unroll
    for (int rep = 0; rep < 2; ++rep) {
        int cid = tid + rep * 256;
        int row = cid >> 2, seg = cid & 3;
        size_t ga = (size_t)(rowBase + row) * K + kt + seg * 8;
        unsigned d = sbu + (row * 56 + seg * 8) * 2;
        cpa16(d, &Ah[ga]);
        cpa16(d + ASZ * 2, &Al[ga]);
    }
#pragma unroll
    for (int rep = 0; rep < 2; ++rep) {
        int cid = tid + rep * 256;
        int row = cid >> 4, seg = cid & 15;
        size_t gb = (size_t)(kt + row) * Nb + colBase + seg * 8;
        cpa16(sbu + (2 * ASZ + row * 136 + seg * 8) * 2, &Bh[gb]);
    }
}

__global__ void __launch_bounds__(256)
gemm_f16_kernel(const ushortT* __restrict__ Ah, const ushortT* __restrict__ Al,
                const ushortT* __restrict__ B0, const ushortT* __restrict__ B1,
                const ushortT* __restrict__ B2,
                float* __restrict__ C0, float* __restrict__ C1, float* __restrict__ C2,
                int t1, int t2, int n0, int n1, int n2, int K)
{
    extern __shared__ ushortT sm[];

    const int tid  = threadIdx.x;
    const int lane = tid & 31;
    const int wid  = tid >> 5;
    const int g    = lane >> 2;
    const int q4   = lane & 3;
    const int warpM = wid >> 1;
    const int warpN = wid & 1;
    const int rowBase = blockIdx.y * 128;

    int ct = blockIdx.x;
    const ushortT* Bh; float* C; int Nb; int ctl;
    if (ct < t1)      { Bh = B0; C = C0; Nb = n0; ctl = ct; }
    else if (ct < t2) { Bh = B1; C = C1; Nb = n1; ctl = ct - t1; }
    else              { Bh = B2; C = C2; Nb = n2; ctl = ct - t2; }
    const int colBase = ctl * 128;

    const int NIT = K >> 5;

    gemm_stage(sm,       Ah, Al, Bh, rowBase, colBase, 0,  K, Nb, tid);
    CP_COMMIT();
    gemm_stage(sm + STG, Ah, Al, Bh, rowBase, colBase, 32, K, Nb, tid);
    CP_COMMIT();

    float acc[2][8][4] = {};

    const int aRow = lane & 15;
    const int aCol = (lane >> 4) << 3;
    const int bRow = (lane & 7) + (((lane >> 3) & 1) << 3);
    const int bCol = (lane >> 4) << 3;

    for (int i = 0; i < NIT; ++i) {
        CP_WAIT1();
        __syncthreads();
        ushortT* sA  = sm + (i & 1) * STG;
        ushortT* sAl = sA + ASZ;
        ushortT* sB  = sA + 2 * ASZ;

#pragma unroll
        for (int ks = 0; ks < 2; ++ks) {
            const int k0 = ks * 16;
            unsigned ah[2][4], al[2][4];
#pragma unroll
            for (int mt = 0; mt < 2; ++mt) {
                int r = warpM * 32 + mt * 16 + aRow;
                ldsm4(ah[mt], saddr(&sA[r * 56 + k0 + aCol]));
                ldsm4(al[mt], saddr(&sAl[r * 56 + k0 + aCol]));
            }
#pragma unroll
            for (int ntp = 0; ntp < 4; ++ntp) {
                int n0b = warpN * 64 + ntp * 16;
                unsigned bh[4];
                ldsm4t(bh, saddr(&sB[(k0 + bRow) * 136 + n0b + bCol]));
#pragma unroll
                for (int mt = 0; mt < 2; ++mt) {
                    mma_f16(acc[mt][2 * ntp],     ah[mt], bh);
                    mma_f16(acc[mt][2 * ntp],     al[mt], bh);
                    mma_f16(acc[mt][2 * ntp + 1], ah[mt], bh + 2);
                    mma_f16(acc[mt][2 * ntp + 1], al[mt], bh + 2);
                }
            }
        }
        __syncthreads();
        if (i + 2 < NIT)
            gemm_stage(sm + (i & 1) * STG, Ah, Al, Bh,
                       rowBase, colBase, (i + 2) * 32, K, Nb, tid);
        CP_COMMIT();
    }

#pragma unroll
    for (int mt = 0; mt < 2; ++mt) {
        int row = rowBase + warpM * 32 + mt * 16 + g;
#pragma unroll
        for (int nt = 0; nt < 8; ++nt) {
            int col = colBase + warpN * 64 + nt * 8 + 2 * q4;
            *(float2*)&C[(size_t)row * Nb + col] =
                make_float2(acc[mt][nt][0], acc[mt][nt][1]);
            *(float2*)&C[(size_t)(row + 8) * Nb + col] =
                make_float2(acc[mt][nt][2], acc[mt][nt][3]);
        }
    }
}

// ============================================================
// RoPE in place on q [MROWS, NH*HD] and k [MROWS, KVH*HD].
// ============================================================
__global__ void rope_kernel(float* __restrict__ q, float* __restrict__ k)
{
    const int QP = MROWS * NH * (HD / 2);
    const int KP = MROWS * KVH * (HD / 2);
    int idx = blockIdx.x * blockDim.x + threadIdx.x;
    if (idx >= QP + KP) return;

    float* buf;
    int row, head, j, rowdim;
    if (idx < QP) {
        int t = idx;
        j = t & 31; t >>= 5;
        head = t & (NH - 1); t >>= 5;
        row = t;
        buf = q; rowdim = NH * HD;
    } else {
        int t = idx - QP;
        j = t & 31; t >>= 5;
        head = t & (KVH - 1); t >>= 3;
        row = t;
        buf = k; rowdim = KVH * HD;
    }
    int pos = row & (SEQ - 1);
    float inv_freq = exp2f(-(float)j * 0.41524101186092029f);
    float ang = (float)pos * inv_freq;
    float c, s;
    sincosf(ang, &s, &c);

    float* p = buf + (size_t)row * rowdim + head * HD + j;
    float x1 = p[0], x2 = p[32];
    p[0]  = x1 * c - x2 * s;
    p[32] = x2 * c + x1 * s;
}

// ============================================================
// Flash attention, fp16 2-term MMA, cp.async double-buffered K/V.
// Grid: (SEQ/128, NH, BATCH). 256 thr = 8 warps, warp owns 16 q rows.
// Smem (fp16, stride 72): QPh/QPl [128][72] (Q staging then P),
// K0,V0,K1,V1 [64][72] = 73728 B.
// Emits fp16 hi/lo att for the out-projection.
// ============================================================
__device__ __forceinline__ void attn_stage(
    ushortT* kdst, ushortT* vdst,
    const ushortT* __restrict__ kg, const ushortT* __restrict__ vg,
    int kb, int tid)
{
    int row = tid >> 2;            // 0..63
    int seg = (tid & 3) * 2;       // 16-elem chunks: 0,2,4,6
    size_t gb = (size_t)(kb + row) * KVDIM + seg * 8;
    unsigned kd = saddr(&kdst[row * 72 + seg * 8]);
    unsigned vd = saddr(&vdst[row * 72 + seg * 8]);
    cpa16(kd,      &kg[gb]);
    cpa16(kd + 16, &kg[gb + 8]);
    cpa16(vd,      &vg[gb]);
    cpa16(vd + 16, &vg[gb + 8]);
}

__global__ void __launch_bounds__(256)
attn_kernel(const float* __restrict__ q,
            const ushortT* __restrict__ kh, const ushortT* __restrict__ vh,
            ushortT* __restrict__ atth, ushortT* __restrict__ attl)
{
    extern __shared__ ushortT smb[];
    ushortT* QPh  = smb;                   // [128][72]
    ushortT* QPl  = QPh + 128 * 72;
    ushortT* KVb  = QPl + 128 * 72;        // K0 V0 K1 V1, each [64][72]

    const int tid  = threadIdx.x;
    const int lane = tid & 31;
    const int wid  = tid >> 5;
    const int g    = lane >> 2;
    const int q4   = lane & 3;
    const int qb   = blockIdx.x * 128;
    const int h    = blockIdx.y;
    const int b    = blockIdx.z;
    const int kvh  = h >> 2;
    const int m0w  = wid * 16;

    const float*   qg  = q  + (size_t)b * SEQ * HID + (size_t)h * HD;
    const ushortT* kgh = kh + (size_t)b * SEQ * KVDIM + (size_t)kvh * HD;
    const ushortT* vgh = vh + (size_t)b * SEQ * KVDIM + (size_t)kvh * HD;
    ushortT* oh = atth + (size_t)b * SEQ * HID + (size_t)h * HD;
    ushortT* ol = attl + (size_t)b * SEQ * HID + (size_t)h * HD;

    // stage Q (128x64), fold 1/8 scale, split to fp16 hi/lo
#pragma unroll
    for (int p = 0; p < 8; ++p) {
        int id = tid + p * 256;
        int m = id >> 4, d4 = (id & 15) * 4;
        float4 vq = *(const float4*)&qg[(size_t)(qb + m) * HID + d4];
        unsigned h0, l0, h1, l1;
        split2h(vq.x * 0.125f, vq.y * 0.125f, h0, l0);
        split2h(vq.z * 0.125f, vq.w * 0.125f, h1, l1);
        *(uint2*)&QPh[m * 72 + d4] = make_uint2(h0, h1);
        *(uint2*)&QPl[m * 72 + d4] = make_uint2(l0, l1);
    }
    // prefetch first K/V tile while Q staging settles
    attn_stage(KVb, KVb + 64 * 72, kgh, vgh, 0, tid);
    CP_COMMIT();
    __syncthreads();

    const int aRow = lane & 15;
    const int aCol = (lane >> 4) << 3;
    const int kRow = (lane & 7) + ((lane >> 4) << 3);
    const int kCol = ((lane >> 3) & 1) << 3;
    const int vRow = (lane & 7) + (((lane >> 3) & 1) << 3);
    const int vCol = (lane >> 4) << 3;

    // hoist Q fragments (hi/lo) into registers, once
    unsigned Qh[4][4], Ql[4][4];
#pragma unroll
    for (int kt = 0; kt < 4; ++kt) {
        ldsm4(Qh[kt], saddr(&QPh[(m0w + aRow) * 72 + kt * 16 + aCol]));
        ldsm4(Ql[kt], saddr(&QPl[(m0w + aRow) * 72 + kt * 16 + aCol]));
    }

    float Oa[8][4] = {};
    float miA = -3.0e38f, miB = -3.0e38f, liA = 0.0f, liB = 0.0f;

    for (int i = 0; i < SEQ / 64; ++i) {
        CP_WAIT0();
        __syncthreads();          // K/V tile (i&1) ready for all threads
        if (i + 1 < SEQ / 64) {
            ushortT* nb = KVb + ((i + 1) & 1) * 2 * 64 * 72;
            attn_stage(nb, nb + 64 * 72, kgh, vgh, (i + 1) * 64, tid);
            CP_COMMIT();
        }
        ushortT* Kc = KVb + (i & 1) * 2 * 64 * 72;
        ushortT* Vc = Kc + 64 * 72;

        // ---- S = Q @ K^T (fp16 2-term) ----
        float S[8][4] = {};
#pragma unroll
        for (int kt = 0; kt < 4; ++kt) {
            int k0 = kt * 16;
#pragma unroll
            for (int ntp = 0; ntp < 4; ++ntp) {
                int n0 = ntp * 16;
                unsigned bh[4];
                ldsm4(bh, saddr(&Kc[(n0 + kRow) * 72 + k0 + kCol]));
                mma_f16(S[2 * ntp],     Qh[kt], bh);
                mma_f16(S[2 * ntp],     Ql[kt], bh);
                mma_f16(S[2 * ntp + 1], Qh[kt], bh + 2);
                mma_f16(S[2 * ntp + 1], Ql[kt], bh + 2);
            }
        }

        // ---- online softmax (rows m0w+g, m0w+8+g) ----
        float mA = -3.0e38f, mB = -3.0e38f;
#pragma unroll
        for (int nt = 0; nt < 8; ++nt) {
            mA = fmaxf(mA, fmaxf(S[nt][0], S[nt][1]));
            mB = fmaxf(mB, fmaxf(S[nt][2], S[nt][3]));
        }
        mA = fmaxf(mA, __shfl_xor_sync(0xffffffffu, mA, 1));
        mA = fmaxf(mA, __shfl_xor_sync(0xffffffffu, mA, 2));
        mB = fmaxf(mB, __shfl_xor_sync(0xffffffffu, mB, 1));
        mB = fmaxf(mB, __shfl_xor_sync(0xffffffffu, mB, 2));

        float mnA = fmaxf(miA, mA), mnB = fmaxf(miB, mB);
        float aA = __expf(miA - mnA), aB = __expf(miB - mnB);
        miA = mnA; miB = mnB;

        float sA = 0.0f, sB = 0.0f;
#pragma unroll
        for (int nt = 0; nt < 8; ++nt) {
            S[nt][0] = __expf(S[nt][0] - mnA);
            S[nt][1] = __expf(S[nt][1] - mnA);
            S[nt][2] = __expf(S[nt][2] - mnB);
            S[nt][3] = __expf(S[nt][3] - mnB);
            sA += S[nt][0] + S[nt][1];
            sB += S[nt][2] + S[nt][3];
        }
        sA += __shfl_xor_sync(0xffffffffu, sA, 1);
        sA += __shfl_xor_sync(0xffffffffu, sA, 2);
        sB += __shfl_xor_sync(0xffffffffu, sB, 1);
        sB += __shfl_xor_sync(0xffffffffu, sB, 2);
        liA = liA * aA + sA;
        liB = liB * aB + sB;

        // rescale O, store P (fp16 hi/lo) into warp-private QP rows
#pragma unroll
        for (int nt = 0; nt < 8; ++nt) {
            Oa[nt][0] *= aA; Oa[nt][1] *= aA;
            Oa[nt][2] *= aB; Oa[nt][3] *= aB;
            int col = nt * 8 + 2 * q4;
            unsigned hp, lp;
            split2h(S[nt][0], S[nt][1], hp, lp);
            *(unsigned*)&QPh[(m0w + g) * 72 + col] = hp;
            *(unsigned*)&QPl[(m0w + g) * 72 + col] = lp;
            split2h(S[nt][2], S[nt][3], hp, lp);
            *(unsigned*)&QPh[(m0w + 8 + g) * 72 + col] = hp;
            *(unsigned*)&QPl[(m0w + 8 + g) * 72 + col] = lp;
        }
        __syncwarp();

        // ---- O += P @ V (fp16 2-term) ----
#pragma unroll
        for (int kt = 0; kt < 4; ++kt) {
            int k0 = kt * 16;
            unsigned ph[4], pl[4];
            ldsm4(ph, saddr(&QPh[(m0w + aRow) * 72 + k0 + aCol]));
            ldsm4(pl, saddr(&QPl[(m0w + aRow) * 72 + k0 + aCol]));
#pragma unroll
            for (int ntp = 0; ntp < 4; ++ntp) {
                int n0 = ntp * 16;
                unsigned bh[4];
                ldsm4t(bh, saddr(&Vc[(k0 + vRow) * 72 + n0 + vCol]));
                mma_f16(Oa[2 * ntp],     ph, bh);
                mma_f16(Oa[2 * ntp],     pl, bh);
                mma_f16(Oa[2 * ntp + 1], ph, bh + 2);
                mma_f16(Oa[2 * ntp + 1], pl, bh + 2);
            }
        }
        __syncthreads();          // all reads of tile (i&1) done before restaging
    }

    // epilogue: normalize, split to fp16 hi/lo
    float invA = 1.0f / liA, invB = 1.0f / liB;
#pragma unroll
    for (int nt = 0; nt < 8; ++nt) {
        int col = nt * 8 + 2 * q4;
        size_t rA = (size_t)(qb + m0w + g) * HID + col;
        size_t rB = (size_t)(qb + m0w + 8 + g) * HID + col;
        unsigned hp, lp;
        split2h(Oa[nt][0] * invA, Oa[nt][1] * invA, hp, lp);
        *(unsigned*)&oh[rA] = hp;
        *(unsigned*)&ol[rA] = lp;
        split2h(Oa[nt][2] * invB, Oa[nt][3] * invB, hp, lp);
        *(unsigned*)&oh[rB] = hp;
        *(unsigned*)&ol[rB] = lp;
    }
}

// ============================================================
// launch
// ============================================================
extern "C" void kernel_launch(void* const* d_in, const int* in_sizes, int n_in,
                              void* d_out, int out_size)
{
    const float* x  = (const float*)d_in[0];
    const float* wq = (const float*)d_in[1];
    const float* wk = (const float*)d_in[2];
    const float* wv = (const float*)d_in[3];
    const float* wo = (const float*)d_in[4];
    float* out = (float*)d_out;

    float *qp, *kp, *vp;
    ushortT *xh, *xl, *wqh, *wkh, *wvh, *woh;
    ushortT *khp, *vhp, *ath, *atl;
    cudaGetSymbolAddress((void**)&qp, g_q);
    cudaGetSymbolAddress((void**)&kp, g_k);
    cudaGetSymbolAddress((void**)&vp, g_v);
    cudaGetSymbolAddress((void**)&xh, g_xh);   cudaGetSymbolAddress((void**)&xl, g_xl);
    cudaGetSymbolAddress((void**)&wqh, g_wqh);
    cudaGetSymbolAddress((void**)&wkh, g_wkh);
    cudaGetSymbolAddress((void**)&wvh, g_wvh);
    cudaGetSymbolAddress((void**)&woh, g_woh);
    cudaGetSymbolAddress((void**)&khp, g_kh);
    cudaGetSymbolAddress((void**)&vhp, g_vh);
    cudaGetSymbolAddress((void**)&ath, g_atth);
    cudaGetSymbolAddress((void**)&atl, g_attl);

    dim3 blk(256);
    const int GEMM_SMEM = 2 * STG * 2;

    // prep: x -> fp16 hi/lo; weights -> fp16 hi
    split_f16hl_kernel<<<(MROWS * HID) / 1024, 256>>>(x, xh, xl, MROWS * HID);
    split_f16h_kernel<<<(HID * HID) / 1024, 256>>>(wq, wqh, HID * HID);
    split_f16h_kernel<<<(HID * KVDIM) / 1024, 256>>>(wk, wkh, HID * KVDIM);
    split_f16h_kernel<<<(HID * KVDIM) / 1024, 256>>>(wv, wvh, HID * KVDIM);
    split_f16h_kernel<<<(HID * HID) / 1024, 256>>>(wo, woh, HID * HID);

    cudaFuncSetAttribute(gemm_f16_kernel, cudaFuncAttributeMaxDynamicSharedMemorySize, GEMM_SMEM);

    // merged QKV projection: [0,16)=Q, [16,20)=K, [20,24)=V
    gemm_f16_kernel<<<dim3(24, MROWS / 128), blk, GEMM_SMEM>>>(
        xh, xl, wqh, wkh, wvh, qp, kp, vp,
        16, 20, HID, KVDIM, KVDIM, HID);

    // RoPE on q, k (fp32)
    int total = MROWS * NH * (HD / 2) + MROWS * KVH * (HD / 2);
    rope_kernel<<<(total + 255) / 256, 256>>>(qp, kp);

    // roped k and v -> fp16 hi only
    split_f16h_kernel<<<(MROWS * KVDIM) / 1024, 256>>>(kp, khp, MROWS * KVDIM);
    split_f16h_kernel<<<(MROWS * KVDIM) / 1024, 256>>>(vp, vhp, MROWS * KVDIM);

    // attention (fp16 2-term, emits fp16 hi/lo att)
    cudaFuncSetAttribute(attn_kernel, cudaFuncAttributeMaxDynamicSharedMemorySize, 73728);
    attn_kernel<<<dim3(SEQ / 128, NH, BATCH), blk, 73728>>>(qp, khp, vhp, ath, atl);

    // output projection -> fp32 d_out
    gemm_f16_kernel<<<dim3(16, MROWS / 128), blk, GEMM_SMEM>>>(
        ath, atl, woh, woh, woh, out, out, out,
        16, 32, HID, HID, HID, HID);
}

// round 16
// speedup vs baseline: 3.8924x; 1.0984x over previous
#include <cuda_runtime.h>
#include <cuda_fp16.h>
#include <math.h>

// ---- problem constants ----
#define HID    2048
#define NH     32
#define KVH    8
#define HD     64
#define BATCH  2
#define SEQ    2048
#define MROWS  (BATCH * SEQ)   // 4096
#define KVDIM  (KVH * HD)      // 512

typedef unsigned short ushortT;

// ---- scratch (device globals: allocation-free) ----
__device__ float   g_q[(size_t)MROWS * HID];
__device__ float   g_k[(size_t)MROWS * KVDIM];
__device__ float   g_v[(size_t)MROWS * KVDIM];

// fp16 operands
__device__ ushortT g_xh[(size_t)MROWS * HID], g_xl[(size_t)MROWS * HID];
__device__ ushortT g_wqh[(size_t)HID * HID];          // [K,N] fp16 hi only
__device__ ushortT g_wkh[(size_t)HID * KVDIM];
__device__ ushortT g_wvh[(size_t)HID * KVDIM];
__device__ ushortT g_woh[(size_t)HID * HID];
__device__ ushortT g_atth[(size_t)MROWS * HID], g_attl[(size_t)MROWS * HID];
__device__ ushortT g_kh[(size_t)MROWS * KVDIM];       // roped K, fp16 hi only
__device__ ushortT g_vh[(size_t)MROWS * KVDIM];       // V, fp16 hi only

// ---- generic helpers ----
__device__ __forceinline__ unsigned saddr(const void* p) {
    return (unsigned)__cvta_generic_to_shared(p);
}
__device__ __forceinline__ void ldsm4(unsigned* r, unsigned a) {
    asm volatile("ldmatrix.sync.aligned.m8n8.x4.shared.b16 {%0,%1,%2,%3}, [%4];"
                 : "=r"(r[0]), "=r"(r[1]), "=r"(r[2]), "=r"(r[3]) : "r"(a));
}
__device__ __forceinline__ void ldsm4t(unsigned* r, unsigned a) {
    asm volatile("ldmatrix.sync.aligned.m8n8.x4.trans.shared.b16 {%0,%1,%2,%3}, [%4];"
                 : "=r"(r[0]), "=r"(r[1]), "=r"(r[2]), "=r"(r[3]) : "r"(a));
}
__device__ __forceinline__ void mma_f16(float* c, const unsigned* a, const unsigned* b) {
    asm volatile(
        "mma.sync.aligned.m16n8k16.row.col.f32.f16.f16.f32 "
        "{%0,%1,%2,%3}, {%4,%5,%6,%7}, {%8,%9}, {%0,%1,%2,%3};"
        : "+f"(c[0]), "+f"(c[1]), "+f"(c[2]), "+f"(c[3])
        : "r"(a[0]), "r"(a[1]), "r"(a[2]), "r"(a[3]), "r"(b[0]), "r"(b[1]));
}
// fp16 hi/lo split of two floats
__device__ __forceinline__ void split2h(float a, float b, unsigned& hp, unsigned& lp) {
    __half ha = __float2half_rn(a), hb = __float2half_rn(b);
    __half la = __float2half_rn(a - __half2float(ha));
    __half lb = __float2half_rn(b - __half2float(hb));
    __half2 hv = __halves2half2(ha, hb), lv = __halves2half2(la, lb);
    hp = *reinterpret_cast<unsigned*>(&hv);
    lp = *reinterpret_cast<unsigned*>(&lv);
}
// fp16 single-rounded pack of two floats
__device__ __forceinline__ unsigned pack2h(float a, float b) {
    __half2 hv = __halves2half2(__float2half_rn(a), __float2half_rn(b));
    return *reinterpret_cast<unsigned*>(&hv);
}
// cp.async 16B
__device__ __forceinline__ void cpa16(unsigned d, const void* s) {
    asm volatile("cp.async.cg.shared.global [%0], [%1], 16;" :: "r"(d), "l"(s) : "memory");
}
#define CP_COMMIT() asm volatile("cp.async.commit_group;" ::: "memory")
#define CP_WAIT1()  asm volatile("cp.async.wait_group 1;" ::: "memory")
#define CP_WAIT0()  asm volatile("cp.async.wait_group 0;" ::: "memory")

// ============================================================
// split kernels
// ============================================================
__global__ void split_f16hl_kernel(const float* __restrict__ in,
                                   ushortT* __restrict__ hi, ushortT* __restrict__ lo,
                                   int n)
{
    int i = (blockIdx.x * blockDim.x + threadIdx.x) * 4;
    if (i >= n) return;
    float4 v = *(const float4*)&in[i];
    unsigned h0, l0, h1, l1;
    split2h(v.x, v.y, h0, l0);
    split2h(v.z, v.w, h1, l1);
    *(uint2*)&hi[i] = make_uint2(h0, h1);
    *(uint2*)&lo[i] = make_uint2(l0, l1);
}
__global__ void split_f16h_kernel(const float* __restrict__ in,
                                  ushortT* __restrict__ hi, int n)
{
    int i = (blockIdx.x * blockDim.x + threadIdx.x) * 4;
    if (i >= n) return;
    float4 v = *(const float4*)&in[i];
    *(uint2*)&hi[i] = make_uint2(pack2h(v.x, v.y), pack2h(v.z, v.w));
}

// ============================================================
// fp16 2-term GEMM with cp.async double buffering + output routing.
// (unchanged — passing component)
// ============================================================
#define ASZ (128 * 56)
#define BSZ (32 * 136)
#define STG (2 * ASZ + BSZ)

__device__ __forceinline__ void gemm_stage(
    ushortT* sb, const ushortT* __restrict__ Ah, const ushortT* __restrict__ Al,
    const ushortT* __restrict__ Bh, int rowBase, int colBase, int kt,
    int K, int Nb, int tid)
{
    unsigned sbu = saddr(sb);
#pragma unroll
    for (int rep = 0; rep < 2; ++rep) {
        int cid = tid + rep * 256;
        int row = cid >> 2, seg = cid & 3;
        size_t ga = (size_t)(rowBase + row) * K + kt + seg * 8;
        unsigned d = sbu + (row * 56 + seg * 8) * 2;
        cpa16(d, &Ah[ga]);
        cpa16(d + ASZ * 2, &Al[ga]);
    }
#pragma unroll
    for (int rep = 0; rep < 2; ++rep) {
        int cid = tid + rep * 256;
        int row = cid >> 4, seg = cid & 15;
        size_t gb = (size_t)(kt + row) * Nb + colBase + seg * 8;
        cpa16(sbu + (2 * ASZ + row * 136 + seg * 8) * 2, &Bh[gb]);
    }
}

__global__ void __launch_bounds__(256)
gemm_f16_kernel(const ushortT* __restrict__ Ah, const ushortT* __restrict__ Al,
                const ushortT* __restrict__ B0, const ushortT* __restrict__ B1,
                const ushortT* __restrict__ B2,
                float* __restrict__ C0, float* __restrict__ C1, float* __restrict__ C2,
                int t1, int t2, int n0, int n1, int n2, int K)
{
    extern __shared__ ushortT sm[];

    const int tid  = threadIdx.x;
    const int lane = tid & 31;
    const int wid  = tid >> 5;
    const int g    = lane >> 2;
    const int q4   = lane & 3;
    const int warpM = wid >> 1;
    const int warpN = wid & 1;
    const int rowBase = blockIdx.y * 128;

    int ct = blockIdx.x;
    const ushortT* Bh; float* C; int Nb; int ctl;
    if (ct < t1)      { Bh = B0; C = C0; Nb = n0; ctl = ct; }
    else if (ct < t2) { Bh = B1; C = C1; Nb = n1; ctl = ct - t1; }
    else              { Bh = B2; C = C2; Nb = n2; ctl = ct - t2; }
    const int colBase = ctl * 128;

    const int NIT = K >> 5;

    gemm_stage(sm,       Ah, Al, Bh, rowBase, colBase, 0,  K, Nb, tid);
    CP_COMMIT();
    gemm_stage(sm + STG, Ah, Al, Bh, rowBase, colBase, 32, K, Nb, tid);
    CP_COMMIT();

    float acc[2][8][4] = {};

    const int aRow = lane & 15;
    const int aCol = (lane >> 4) << 3;
    const int bRow = (lane & 7) + (((lane >> 3) & 1) << 3);
    const int bCol = (lane >> 4) << 3;

    for (int i = 0; i < NIT; ++i) {
        CP_WAIT1();
        __syncthreads();
        ushortT* sA  = sm + (i & 1) * STG;
        ushortT* sAl = sA + ASZ;
        ushortT* sB  = sA + 2 * ASZ;

#pragma unroll
        for (int ks = 0; ks < 2; ++ks) {
            const int k0 = ks * 16;
            unsigned ah[2][4], al[2][4];
#pragma unroll
            for (int mt = 0; mt < 2; ++mt) {
                int r = warpM * 32 + mt * 16 + aRow;
                ldsm4(ah[mt], saddr(&sA[r * 56 + k0 + aCol]));
                ldsm4(al[mt], saddr(&sAl[r * 56 + k0 + aCol]));
            }
#pragma unroll
            for (int ntp = 0; ntp < 4; ++ntp) {
                int n0b = warpN * 64 + ntp * 16;
                unsigned bh[4];
                ldsm4t(bh, saddr(&sB[(k0 + bRow) * 136 + n0b + bCol]));
#pragma unroll
                for (int mt = 0; mt < 2; ++mt) {
                    mma_f16(acc[mt][2 * ntp],     ah[mt], bh);
                    mma_f16(acc[mt][2 * ntp],     al[mt], bh);
                    mma_f16(acc[mt][2 * ntp + 1], ah[mt], bh + 2);
                    mma_f16(acc[mt][2 * ntp + 1], al[mt], bh + 2);
                }
            }
        }
        __syncthreads();
        if (i + 2 < NIT)
            gemm_stage(sm + (i & 1) * STG, Ah, Al, Bh,
                       rowBase, colBase, (i + 2) * 32, K, Nb, tid);
        CP_COMMIT();
    }

#pragma unroll
    for (int mt = 0; mt < 2; ++mt) {
        int row = rowBase + warpM * 32 + mt * 16 + g;
#pragma unroll
        for (int nt = 0; nt < 8; ++nt) {
            int col = colBase + warpN * 64 + nt * 8 + 2 * q4;
            *(float2*)&C[(size_t)row * Nb + col] =
                make_float2(acc[mt][nt][0], acc[mt][nt][1]);
            *(float2*)&C[(size_t)(row + 8) * Nb + col] =
                make_float2(acc[mt][nt][2], acc[mt][nt][3]);
        }
    }
}

// ============================================================
// RoPE in place on q [MROWS, NH*HD] and k [MROWS, KVH*HD].
// ============================================================
__global__ void rope_kernel(float* __restrict__ q, float* __restrict__ k)
{
    const int QP = MROWS * NH * (HD / 2);
    const int KP = MROWS * KVH * (HD / 2);
    int idx = blockIdx.x * blockDim.x + threadIdx.x;
    if (idx >= QP + KP) return;

    float* buf;
    int row, head, j, rowdim;
    if (idx < QP) {
        int t = idx;
        j = t & 31; t >>= 5;
        head = t & (NH - 1); t >>= 5;
        row = t;
        buf = q; rowdim = NH * HD;
    } else {
        int t = idx - QP;
        j = t & 31; t >>= 5;
        head = t & (KVH - 1); t >>= 3;
        row = t;
        buf = k; rowdim = KVH * HD;
    }
    int pos = row & (SEQ - 1);
    float inv_freq = exp2f(-(float)j * 0.41524101186092029f);
    float ang = (float)pos * inv_freq;
    float c, s;
    sincosf(ang, &s, &c);

    float* p = buf + (size_t)row * rowdim + head * HD + j;
    float x1 = p[0], x2 = p[32];
    p[0]  = x1 * c - x2 * s;
    p[32] = x2 * c + x1 * s;
}

// ============================================================
// Flash attention, fp16 MMA: QK^T 2-term, PV 1-term (P single-rounded).
// cp.async double-buffered K/V, ONE __syncthreads per kb-iteration.
// Grid: (SEQ/128, NH, BATCH). 256 thr = 8 warps, warp owns 16 q rows.
// Smem: QPh/QPl [128][72] (Q staging; QPh then reused for P hi),
// K0,V0,K1,V1 [64][72] = 73728 B.
// ============================================================
__device__ __forceinline__ void attn_stage(
    ushortT* kdst, ushortT* vdst,
    const ushortT* __restrict__ kg, const ushortT* __restrict__ vg,
    int kb, int tid)
{
    int row = tid >> 2;            // 0..63
    int seg = (tid & 3) * 2;       // 16-elem chunks
    size_t gb = (size_t)(kb + row) * KVDIM + seg * 8;
    unsigned kd = saddr(&kdst[row * 72 + seg * 8]);
    unsigned vd = saddr(&vdst[row * 72 + seg * 8]);
    cpa16(kd,      &kg[gb]);
    cpa16(kd + 16, &kg[gb + 8]);
    cpa16(vd,      &vg[gb]);
    cpa16(vd + 16, &vg[gb + 8]);
}

__global__ void __launch_bounds__(256)
attn_kernel(const float* __restrict__ q,
            const ushortT* __restrict__ kh, const ushortT* __restrict__ vh,
            ushortT* __restrict__ atth, ushortT* __restrict__ attl)
{
    extern __shared__ ushortT smb[];
    ushortT* QPh  = smb;                   // [128][72]: Q hi staging, then P
    ushortT* QPl  = QPh + 128 * 72;        // [128][72]: Q lo staging
    ushortT* KVb  = QPl + 128 * 72;        // K0 V0 K1 V1, each [64][72]

    const int tid  = threadIdx.x;
    const int lane = tid & 31;
    const int wid  = tid >> 5;
    const int g    = lane >> 2;
    const int q4   = lane & 3;
    const int qb   = blockIdx.x * 128;
    const int h    = blockIdx.y;
    const int b    = blockIdx.z;
    const int kvh  = h >> 2;
    const int m0w  = wid * 16;

    const float*   qg  = q  + (size_t)b * SEQ * HID + (size_t)h * HD;
    const ushortT* kgh = kh + (size_t)b * SEQ * KVDIM + (size_t)kvh * HD;
    const ushortT* vgh = vh + (size_t)b * SEQ * KVDIM + (size_t)kvh * HD;
    ushortT* oh = atth + (size_t)b * SEQ * HID + (size_t)h * HD;
    ushortT* ol = attl + (size_t)b * SEQ * HID + (size_t)h * HD;

    // stage Q (128x64), fold 1/8 scale, split to fp16 hi/lo
#pragma unroll
    for (int p = 0; p < 8; ++p) {
        int id = tid + p * 256;
        int m = id >> 4, d4 = (id & 15) * 4;
        float4 vq = *(const float4*)&qg[(size_t)(qb + m) * HID + d4];
        unsigned h0, l0, h1, l1;
        split2h(vq.x * 0.125f, vq.y * 0.125f, h0, l0);
        split2h(vq.z * 0.125f, vq.w * 0.125f, h1, l1);
        *(uint2*)&QPh[m * 72 + d4] = make_uint2(h0, h1);
        *(uint2*)&QPl[m * 72 + d4] = make_uint2(l0, l1);
    }
    // prefetch first K/V tile
    attn_stage(KVb, KVb + 64 * 72, kgh, vgh, 0, tid);
    CP_COMMIT();
    __syncthreads();

    const int aRow = lane & 15;
    const int aCol = (lane >> 4) << 3;
    const int kRow = (lane & 7) + ((lane >> 4) << 3);
    const int kCol = ((lane >> 3) & 1) << 3;
    const int vRow = (lane & 7) + (((lane >> 3) & 1) << 3);
    const int vCol = (lane >> 4) << 3;

    // hoist Q fragments (hi/lo) into registers, once
    unsigned Qh[4][4], Ql[4][4];
#pragma unroll
    for (int kt = 0; kt < 4; ++kt) {
        ldsm4(Qh[kt], saddr(&QPh[(m0w + aRow) * 72 + kt * 16 + aCol]));
        ldsm4(Ql[kt], saddr(&QPl[(m0w + aRow) * 72 + kt * 16 + aCol]));
    }

    float Oa[8][4] = {};
    float miA = -3.0e38f, miB = -3.0e38f, liA = 0.0f, liB = 0.0f;

    for (int i = 0; i < SEQ / 64; ++i) {
        CP_WAIT0();
        __syncthreads();   // tile (i&1) visible to all; all prior reads of
                           // buffer ((i+1)&1) finished (iter i-1 completed)
        if (i + 1 < SEQ / 64) {
            ushortT* nb = KVb + ((i + 1) & 1) * 2 * 64 * 72;
            attn_stage(nb, nb + 64 * 72, kgh, vgh, (i + 1) * 64, tid);
            CP_COMMIT();
        }
        ushortT* Kc = KVb + (i & 1) * 2 * 64 * 72;
        ushortT* Vc = Kc + 64 * 72;

        // ---- S = Q @ K^T (fp16 2-term) ----
        float S[8][4] = {};
#pragma unroll
        for (int kt = 0; kt < 4; ++kt) {
            int k0 = kt * 16;
#pragma unroll
            for (int ntp = 0; ntp < 4; ++ntp) {
                int n0 = ntp * 16;
                unsigned bh[4];
                ldsm4(bh, saddr(&Kc[(n0 + kRow) * 72 + k0 + kCol]));
                mma_f16(S[2 * ntp],     Qh[kt], bh);
                mma_f16(S[2 * ntp],     Ql[kt], bh);
                mma_f16(S[2 * ntp + 1], Qh[kt], bh + 2);
                mma_f16(S[2 * ntp + 1], Ql[kt], bh + 2);
            }
        }

        // ---- online softmax (rows m0w+g, m0w+8+g) ----
        float mA = -3.0e38f, mB = -3.0e38f;
#pragma unroll
        for (int nt = 0; nt < 8; ++nt) {
            mA = fmaxf(mA, fmaxf(S[nt][0], S[nt][1]));
            mB = fmaxf(mB, fmaxf(S[nt][2], S[nt][3]));
        }
        mA = fmaxf(mA, __shfl_xor_sync(0xffffffffu, mA, 1));
        mA = fmaxf(mA, __shfl_xor_sync(0xffffffffu, mA, 2));
        mB = fmaxf(mB, __shfl_xor_sync(0xffffffffu, mB, 1));
        mB = fmaxf(mB, __shfl_xor_sync(0xffffffffu, mB, 2));

        float mnA = fmaxf(miA, mA), mnB = fmaxf(miB, mB);
        float aA = __expf(miA - mnA), aB = __expf(miB - mnB);
        miA = mnA; miB = mnB;

        float sA = 0.0f, sB = 0.0f;
#pragma unroll
        for (int nt = 0; nt < 8; ++nt) {
            S[nt][0] = __expf(S[nt][0] - mnA);
            S[nt][1] = __expf(S[nt][1] - mnA);
            S[nt][2] = __expf(S[nt][2] - mnB);
            S[nt][3] = __expf(S[nt][3] - mnB);
            sA += S[nt][0] + S[nt][1];
            sB += S[nt][2] + S[nt][3];
        }
        sA += __shfl_xor_sync(0xffffffffu, sA, 1);
        sA += __shfl_xor_sync(0xffffffffu, sA, 2);
        sB += __shfl_xor_sync(0xffffffffu, sB, 1);
        sB += __shfl_xor_sync(0xffffffffu, sB, 2);
        liA = liA * aA + sA;
        liB = liB * aB + sB;

        // rescale O, store P (fp16, single-rounded) into warp-private rows
#pragma unroll
        for (int nt = 0; nt < 8; ++nt) {
            Oa[nt][0] *= aA; Oa[nt][1] *= aA;
            Oa[nt][2] *= aB; Oa[nt][3] *= aB;
            int col = nt * 8 + 2 * q4;
            *(unsigned*)&QPh[(m0w + g) * 72 + col]     = pack2h(S[nt][0], S[nt][1]);
            *(unsigned*)&QPh[(m0w + 8 + g) * 72 + col] = pack2h(S[nt][2], S[nt][3]);
        }
        __syncwarp();

        // ---- O += P @ V (fp16 1-term) ----
#pragma unroll
        for (int kt = 0; kt < 4; ++kt) {
            int k0 = kt * 16;
            unsigned ph[4];
            ldsm4(ph, saddr(&QPh[(m0w + aRow) * 72 + k0 + aCol]));
#pragma unroll
            for (int ntp = 0; ntp < 4; ++ntp) {
                int n0 = ntp * 16;
                unsigned bh[4];
                ldsm4t(bh, saddr(&Vc[(k0 + vRow) * 72 + n0 + vCol]));
                mma_f16(Oa[2 * ntp],     ph, bh);
                mma_f16(Oa[2 * ntp + 1], ph, bh + 2);
            }
        }
        // no bottom sync: next iter's top __syncthreads orders buffer reuse
    }

    // epilogue: normalize, split to fp16 hi/lo
    float invA = 1.0f / liA, invB = 1.0f / liB;
#pragma unroll
    for (int nt = 0; nt < 8; ++nt) {
        int col = nt * 8 + 2 * q4;
        size_t rA = (size_t)(qb + m0w + g) * HID + col;
        size_t rB = (size_t)(qb + m0w + 8 + g) * HID + col;
        unsigned hp, lp;
        split2h(Oa[nt][0] * invA, Oa[nt][1] * invA, hp, lp);
        *(unsigned*)&oh[rA] = hp;
        *(unsigned*)&ol[rA] = lp;
        split2h(Oa[nt][2] * invB, Oa[nt][3] * invB, hp, lp);
        *(unsigned*)&oh[rB] = hp;
        *(unsigned*)&ol[rB] = lp;
    }
}

// ============================================================
// launch
// ============================================================
extern "C" void kernel_launch(void* const* d_in, const int* in_sizes, int n_in,
                              void* d_out, int out_size)
{
    const float* x  = (const float*)d_in[0];
    const float* wq = (const float*)d_in[1];
    const float* wk = (const float*)d_in[2];
    const float* wv = (const float*)d_in[3];
    const float* wo = (const float*)d_in[4];
    float* out = (float*)d_out;

    float *qp, *kp, *vp;
    ushortT *xh, *xl, *wqh, *wkh, *wvh, *woh;
    ushortT *khp, *vhp, *ath, *atl;
    cudaGetSymbolAddress((void**)&qp, g_q);
    cudaGetSymbolAddress((void**)&kp, g_k);
    cudaGetSymbolAddress((void**)&vp, g_v);
    cudaGetSymbolAddress((void**)&xh, g_xh);   cudaGetSymbolAddress((void**)&xl, g_xl);
    cudaGetSymbolAddress((void**)&wqh, g_wqh);
    cudaGetSymbolAddress((void**)&wkh, g_wkh);
    cudaGetSymbolAddress((void**)&wvh, g_wvh);
    cudaGetSymbolAddress((void**)&woh, g_woh);
    cudaGetSymbolAddress((void**)&khp, g_kh);
    cudaGetSymbolAddress((void**)&vhp, g_vh);
    cudaGetSymbolAddress((void**)&ath, g_atth);
    cudaGetSymbolAddress((void**)&atl, g_attl);

    dim3 blk(256);
    const int GEMM_SMEM = 2 * STG * 2;

    // prep: x -> fp16 hi/lo; weights -> fp16 hi
    split_f16hl_kernel<<<(MROWS * HID) / 1024, 256>>>(x, xh, xl, MROWS * HID);
    split_f16h_kernel<<<(HID * HID) / 1024, 256>>>(wq, wqh, HID * HID);
    split_f16h_kernel<<<(HID * KVDIM) / 1024, 256>>>(wk, wkh, HID * KVDIM);
    split_f16h_kernel<<<(HID * KVDIM) / 1024, 256>>>(wv, wvh, HID * KVDIM);
    split_f16h_kernel<<<(HID * HID) / 1024, 256>>>(wo, woh, HID * HID);

    cudaFuncSetAttribute(gemm_f16_kernel, cudaFuncAttributeMaxDynamicSharedMemorySize, GEMM_SMEM);

    // merged QKV projection: [0,16)=Q, [16,20)=K, [20,24)=V
    gemm_f16_kernel<<<dim3(24, MROWS / 128), blk, GEMM_SMEM>>>(
        xh, xl, wqh, wkh, wvh, qp, kp, vp,
        16, 20, HID, KVDIM, KVDIM, HID);

    // RoPE on q, k (fp32)
    int total = MROWS * NH * (HD / 2) + MROWS * KVH * (HD / 2);
    rope_kernel<<<(total + 255) / 256, 256>>>(qp, kp);

    // roped k and v -> fp16 hi only
    split_f16h_kernel<<<(MROWS * KVDIM) / 1024, 256>>>(kp, khp, MROWS * KVDIM);
    split_f16h_kernel<<<(MROWS * KVDIM) / 1024, 256>>>(vp, vhp, MROWS * KVDIM);

    // attention
    cudaFuncSetAttribute(attn_kernel, cudaFuncAttributeMaxDynamicSharedMemorySize, 73728);
    attn_kernel<<<dim3(SEQ / 128, NH, BATCH), blk, 73728>>>(qp, khp, vhp, ath, atl);

    // output projection -> fp32 d_out
    gemm_f16_kernel<<<dim3(16, MROWS / 128), blk, GEMM_SMEM>>>(
        ath, atl, woh, woh, woh, out, out, out,
        16, 32, HID, HID, HID, HID);
}

// round 17
// speedup vs baseline: 5.6392x; 1.4488x over previous
#include <cuda_runtime.h>
#include <cuda_fp16.h>
#include <math.h>

// ---- problem constants ----
#define HID    2048
#define NH     32
#define KVH    8
#define HD     64
#define BATCH  2
#define SEQ    2048
#define MROWS  (BATCH * SEQ)   // 4096
#define KVDIM  (KVH * HD)      // 512

typedef unsigned short ushortT;

// ---- scratch (device globals: allocation-free) ----
__device__ float   g_q[(size_t)MROWS * HID];
__device__ float   g_k[(size_t)MROWS * KVDIM];
__device__ float   g_v[(size_t)MROWS * KVDIM];

// fp16 operands (all single-rounded now)
__device__ ushortT g_xh[(size_t)MROWS * HID];
__device__ ushortT g_wqh[(size_t)HID * HID];          // [K,N] fp16
__device__ ushortT g_wkh[(size_t)HID * KVDIM];
__device__ ushortT g_wvh[(size_t)HID * KVDIM];
__device__ ushortT g_woh[(size_t)HID * HID];
__device__ ushortT g_atth[(size_t)MROWS * HID];
__device__ ushortT g_kh[(size_t)MROWS * KVDIM];       // roped K, fp16
__device__ ushortT g_vh[(size_t)MROWS * KVDIM];       // V, fp16

// ---- generic helpers ----
__device__ __forceinline__ unsigned saddr(const void* p) {
    return (unsigned)__cvta_generic_to_shared(p);
}
__device__ __forceinline__ void ldsm4(unsigned* r, unsigned a) {
    asm volatile("ldmatrix.sync.aligned.m8n8.x4.shared.b16 {%0,%1,%2,%3}, [%4];"
                 : "=r"(r[0]), "=r"(r[1]), "=r"(r[2]), "=r"(r[3]) : "r"(a));
}
__device__ __forceinline__ void ldsm4t(unsigned* r, unsigned a) {
    asm volatile("ldmatrix.sync.aligned.m8n8.x4.trans.shared.b16 {%0,%1,%2,%3}, [%4];"
                 : "=r"(r[0]), "=r"(r[1]), "=r"(r[2]), "=r"(r[3]) : "r"(a));
}
__device__ __forceinline__ void mma_f16(float* c, const unsigned* a, const unsigned* b) {
    asm volatile(
        "mma.sync.aligned.m16n8k16.row.col.f32.f16.f16.f32 "
        "{%0,%1,%2,%3}, {%4,%5,%6,%7}, {%8,%9}, {%0,%1,%2,%3};"
        : "+f"(c[0]), "+f"(c[1]), "+f"(c[2]), "+f"(c[3])
        : "r"(a[0]), "r"(a[1]), "r"(a[2]), "r"(a[3]), "r"(b[0]), "r"(b[1]));
}
// fp16 single-rounded pack of two floats
__device__ __forceinline__ unsigned pack2h(float a, float b) {
    __half2 hv = __halves2half2(__float2half_rn(a), __float2half_rn(b));
    return *reinterpret_cast<unsigned*>(&hv);
}
// cp.async 16B
__device__ __forceinline__ void cpa16(unsigned d, const void* s) {
    asm volatile("cp.async.cg.shared.global [%0], [%1], 16;" :: "r"(d), "l"(s) : "memory");
}
#define CP_COMMIT() asm volatile("cp.async.commit_group;" ::: "memory")
#define CP_WAIT1()  asm volatile("cp.async.wait_group 1;" ::: "memory")
#define CP_WAIT0()  asm volatile("cp.async.wait_group 0;" ::: "memory")

// ============================================================
// split kernel: fp32 -> fp16 (single-rounded)
// ============================================================
__global__ void split_f16h_kernel(const float* __restrict__ in,
                                  ushortT* __restrict__ hi, int n)
{
    int i = (blockIdx.x * blockDim.x + threadIdx.x) * 4;
    if (i >= n) return;
    float4 v = *(const float4*)&in[i];
    *(uint2*)&hi[i] = make_uint2(pack2h(v.x, v.y), pack2h(v.z, v.w));
}

// ============================================================
// fp16 1-term GEMM with cp.async double buffering + output routing.
// C_seg[M,n_seg](f32) = A[M,K] @ B_seg[K,n_seg].
// 128x128 tile, BK=32, 256 thr = 8 warps (4M x 2N).
// Per-stage smem: A[128*56] + B[32*136] fp16 = 23040 B; x2 stages.
// ============================================================
#define ASZ (128 * 56)
#define BSZ (32 * 136)
#define STG (ASZ + BSZ)

__device__ __forceinline__ void gemm_stage(
    ushortT* sb, const ushortT* __restrict__ Ah, const ushortT* __restrict__ Bh,
    int rowBase, int colBase, int kt, int K, int Nb, int tid)
{
    unsigned sbu = saddr(sb);
#pragma unroll
    for (int rep = 0; rep < 2; ++rep) {
        int cid = tid + rep * 256;          // A: 512 chunks of 8 fp16
        int row = cid >> 2, seg = cid & 3;
        size_t ga = (size_t)(rowBase + row) * K + kt + seg * 8;
        cpa16(sbu + (row * 56 + seg * 8) * 2, &Ah[ga]);
    }
#pragma unroll
    for (int rep = 0; rep < 2; ++rep) {
        int cid = tid + rep * 256;          // B: 512 chunks of 8 fp16
        int row = cid >> 4, seg = cid & 15;
        size_t gb = (size_t)(kt + row) * Nb + colBase + seg * 8;
        cpa16(sbu + (ASZ + row * 136 + seg * 8) * 2, &Bh[gb]);
    }
}

__global__ void __launch_bounds__(256)
gemm_f16_kernel(const ushortT* __restrict__ Ah,
                const ushortT* __restrict__ B0, const ushortT* __restrict__ B1,
                const ushortT* __restrict__ B2,
                float* __restrict__ C0, float* __restrict__ C1, float* __restrict__ C2,
                int t1, int t2, int n0, int n1, int n2, int K)
{
    extern __shared__ ushortT sm[];

    const int tid  = threadIdx.x;
    const int lane = tid & 31;
    const int wid  = tid >> 5;
    const int g    = lane >> 2;
    const int q4   = lane & 3;
    const int warpM = wid >> 1;
    const int warpN = wid & 1;
    const int rowBase = blockIdx.y * 128;

    int ct = blockIdx.x;
    const ushortT* Bh; float* C; int Nb; int ctl;
    if (ct < t1)      { Bh = B0; C = C0; Nb = n0; ctl = ct; }
    else if (ct < t2) { Bh = B1; C = C1; Nb = n1; ctl = ct - t1; }
    else              { Bh = B2; C = C2; Nb = n2; ctl = ct - t2; }
    const int colBase = ctl * 128;

    const int NIT = K >> 5;

    gemm_stage(sm,       Ah, Bh, rowBase, colBase, 0,  K, Nb, tid);
    CP_COMMIT();
    gemm_stage(sm + STG, Ah, Bh, rowBase, colBase, 32, K, Nb, tid);
    CP_COMMIT();

    float acc[2][8][4] = {};

    const int aRow = lane & 15;
    const int aCol = (lane >> 4) << 3;
    const int bRow = (lane & 7) + (((lane >> 3) & 1) << 3);
    const int bCol = (lane >> 4) << 3;

    for (int i = 0; i < NIT; ++i) {
        CP_WAIT1();
        __syncthreads();
        ushortT* sA = sm + (i & 1) * STG;
        ushortT* sB = sA + ASZ;

#pragma unroll
        for (int ks = 0; ks < 2; ++ks) {
            const int k0 = ks * 16;
            unsigned ah[2][4];
#pragma unroll
            for (int mt = 0; mt < 2; ++mt) {
                int r = warpM * 32 + mt * 16 + aRow;
                ldsm4(ah[mt], saddr(&sA[r * 56 + k0 + aCol]));
            }
#pragma unroll
            for (int ntp = 0; ntp < 4; ++ntp) {
                int n0b = warpN * 64 + ntp * 16;
                unsigned bh[4];
                ldsm4t(bh, saddr(&sB[(k0 + bRow) * 136 + n0b + bCol]));
#pragma unroll
                for (int mt = 0; mt < 2; ++mt) {
                    mma_f16(acc[mt][2 * ntp],     ah[mt], bh);
                    mma_f16(acc[mt][2 * ntp + 1], ah[mt], bh + 2);
                }
            }
        }
        __syncthreads();
        if (i + 2 < NIT)
            gemm_stage(sm + (i & 1) * STG, Ah, Bh,
                       rowBase, colBase, (i + 2) * 32, K, Nb, tid);
        CP_COMMIT();
    }

#pragma unroll
    for (int mt = 0; mt < 2; ++mt) {
        int row = rowBase + warpM * 32 + mt * 16 + g;
#pragma unroll
        for (int nt = 0; nt < 8; ++nt) {
            int col = colBase + warpN * 64 + nt * 8 + 2 * q4;
            *(float2*)&C[(size_t)row * Nb + col] =
                make_float2(acc[mt][nt][0], acc[mt][nt][1]);
            *(float2*)&C[(size_t)(row + 8) * Nb + col] =
                make_float2(acc[mt][nt][2], acc[mt][nt][3]);
        }
    }
}

// ============================================================
// RoPE in place on q [MROWS, NH*HD] and k [MROWS, KVH*HD].
// ============================================================
__global__ void rope_kernel(float* __restrict__ q, float* __restrict__ k)
{
    const int QP = MROWS * NH * (HD / 2);
    const int KP = MROWS * KVH * (HD / 2);
    int idx = blockIdx.x * blockDim.x + threadIdx.x;
    if (idx >= QP + KP) return;

    float* buf;
    int row, head, j, rowdim;
    if (idx < QP) {
        int t = idx;
        j = t & 31; t >>= 5;
        head = t & (NH - 1); t >>= 5;
        row = t;
        buf = q; rowdim = NH * HD;
    } else {
        int t = idx - QP;
        j = t & 31; t >>= 5;
        head = t & (KVH - 1); t >>= 3;
        row = t;
        buf = k; rowdim = KVH * HD;
    }
    int pos = row & (SEQ - 1);
    float inv_freq = exp2f(-(float)j * 0.41524101186092029f);
    float ang = (float)pos * inv_freq;
    float c, s;
    sincosf(ang, &s, &c);

    float* p = buf + (size_t)row * rowdim + head * HD + j;
    float x1 = p[0], x2 = p[32];
    p[0]  = x1 * c - x2 * s;
    p[32] = x2 * c + x1 * s;
}

// ============================================================
// Flash attention, fp16 single-rounded MMA (QK^T 1-term, PV 1-term).
// cp.async double-buffered K/V, one __syncthreads per kb-iteration.
// Grid: (SEQ/128, NH, BATCH). 256 thr = 8 warps, warp owns 16 q rows.
// Smem: QP [128][72] (Q staging, reused for P), K0,V0,K1,V1 [64][72]
//     = 55296 B.
// ============================================================
__device__ __forceinline__ void attn_stage(
    ushortT* kdst, ushortT* vdst,
    const ushortT* __restrict__ kg, const ushortT* __restrict__ vg,
    int kb, int tid)
{
    int row = tid >> 2;
    int seg = (tid & 3) * 2;
    size_t gb = (size_t)(kb + row) * KVDIM + seg * 8;
    unsigned kd = saddr(&kdst[row * 72 + seg * 8]);
    unsigned vd = saddr(&vdst[row * 72 + seg * 8]);
    cpa16(kd,      &kg[gb]);
    cpa16(kd + 16, &kg[gb + 8]);
    cpa16(vd,      &vg[gb]);
    cpa16(vd + 16, &vg[gb + 8]);
}

__global__ void __launch_bounds__(256)
attn_kernel(const float* __restrict__ q,
            const ushortT* __restrict__ kh, const ushortT* __restrict__ vh,
            ushortT* __restrict__ atth)
{
    extern __shared__ ushortT smb[];
    ushortT* QP  = smb;                    // [128][72]: Q staging, then P
    ushortT* KVb = QP + 128 * 72;          // K0 V0 K1 V1, each [64][72]

    const int tid  = threadIdx.x;
    const int lane = tid & 31;
    const int wid  = tid >> 5;
    const int g    = lane >> 2;
    const int q4   = lane & 3;
    const int qb   = blockIdx.x * 128;
    const int h    = blockIdx.y;
    const int b    = blockIdx.z;
    const int kvh  = h >> 2;
    const int m0w  = wid * 16;

    const float*   qg  = q  + (size_t)b * SEQ * HID + (size_t)h * HD;
    const ushortT* kgh = kh + (size_t)b * SEQ * KVDIM + (size_t)kvh * HD;
    const ushortT* vgh = vh + (size_t)b * SEQ * KVDIM + (size_t)kvh * HD;
    ushortT* oh = atth + (size_t)b * SEQ * HID + (size_t)h * HD;

    // stage Q (128x64), fold 1/8 scale, single-round to fp16
#pragma unroll
    for (int p = 0; p < 8; ++p) {
        int id = tid + p * 256;
        int m = id >> 4, d4 = (id & 15) * 4;
        float4 vq = *(const float4*)&qg[(size_t)(qb + m) * HID + d4];
        *(uint2*)&QP[m * 72 + d4] = make_uint2(
            pack2h(vq.x * 0.125f, vq.y * 0.125f),
            pack2h(vq.z * 0.125f, vq.w * 0.125f));
    }
    // prefetch first K/V tile
    attn_stage(KVb, KVb + 64 * 72, kgh, vgh, 0, tid);
    CP_COMMIT();
    __syncthreads();

    const int aRow = lane & 15;
    const int aCol = (lane >> 4) << 3;
    const int kRow = (lane & 7) + ((lane >> 4) << 3);
    const int kCol = ((lane >> 3) & 1) << 3;
    const int vRow = (lane & 7) + (((lane >> 3) & 1) << 3);
    const int vCol = (lane >> 4) << 3;

    // hoist Q fragments into registers, once
    unsigned Qh[4][4];
#pragma unroll
    for (int kt = 0; kt < 4; ++kt)
        ldsm4(Qh[kt], saddr(&QP[(m0w + aRow) * 72 + kt * 16 + aCol]));

    float Oa[8][4] = {};
    float miA = -3.0e38f, miB = -3.0e38f, liA = 0.0f, liB = 0.0f;

    for (int i = 0; i < SEQ / 64; ++i) {
        CP_WAIT0();
        __syncthreads();
        if (i + 1 < SEQ / 64) {
            ushortT* nb = KVb + ((i + 1) & 1) * 2 * 64 * 72;
            attn_stage(nb, nb + 64 * 72, kgh, vgh, (i + 1) * 64, tid);
            CP_COMMIT();
        }
        ushortT* Kc = KVb + (i & 1) * 2 * 64 * 72;
        ushortT* Vc = Kc + 64 * 72;

        // ---- S = Q @ K^T (fp16 1-term) ----
        float S[8][4] = {};
#pragma unroll
        for (int kt = 0; kt < 4; ++kt) {
            int k0 = kt * 16;
#pragma unroll
            for (int ntp = 0; ntp < 4; ++ntp) {
                int n0 = ntp * 16;
                unsigned bh[4];
                ldsm4(bh, saddr(&Kc[(n0 + kRow) * 72 + k0 + kCol]));
                mma_f16(S[2 * ntp],     Qh[kt], bh);
                mma_f16(S[2 * ntp + 1], Qh[kt], bh + 2);
            }
        }

        // ---- online softmax (rows m0w+g, m0w+8+g) ----
        float mA = -3.0e38f, mB = -3.0e38f;
#pragma unroll
        for (int nt = 0; nt < 8; ++nt) {
            mA = fmaxf(mA, fmaxf(S[nt][0], S[nt][1]));
            mB = fmaxf(mB, fmaxf(S[nt][2], S[nt][3]));
        }
        mA = fmaxf(mA, __shfl_xor_sync(0xffffffffu, mA, 1));
        mA = fmaxf(mA, __shfl_xor_sync(0xffffffffu, mA, 2));
        mB = fmaxf(mB, __shfl_xor_sync(0xffffffffu, mB, 1));
        mB = fmaxf(mB, __shfl_xor_sync(0xffffffffu, mB, 2));

        float mnA = fmaxf(miA, mA), mnB = fmaxf(miB, mB);
        float aA = __expf(miA - mnA), aB = __expf(miB - mnB);
        miA = mnA; miB = mnB;

        float sA = 0.0f, sB = 0.0f;
#pragma unroll
        for (int nt = 0; nt < 8; ++nt) {
            S[nt][0] = __expf(S[nt][0] - mnA);
            S[nt][1] = __expf(S[nt][1] - mnA);
            S[nt][2] = __expf(S[nt][2] - mnB);
            S[nt][3] = __expf(S[nt][3] - mnB);
            sA += S[nt][0] + S[nt][1];
            sB += S[nt][2] + S[nt][3];
        }
        sA += __shfl_xor_sync(0xffffffffu, sA, 1);
        sA += __shfl_xor_sync(0xffffffffu, sA, 2);
        sB += __shfl_xor_sync(0xffffffffu, sB, 1);
        sB += __shfl_xor_sync(0xffffffffu, sB, 2);
        liA = liA * aA + sA;
        liB = liB * aB + sB;

        // rescale O, store P (fp16) into warp-private rows
#pragma unroll
        for (int nt = 0; nt < 8; ++nt) {
            Oa[nt][0] *= aA; Oa[nt][1] *= aA;
            Oa[nt][2] *= aB; Oa[nt][3] *= aB;
            int col = nt * 8 + 2 * q4;
            *(unsigned*)&QP[(m0w + g) * 72 + col]     = pack2h(S[nt][0], S[nt][1]);
            *(unsigned*)&QP[(m0w + 8 + g) * 72 + col] = pack2h(S[nt][2], S[nt][3]);
        }
        __syncwarp();

        // ---- O += P @ V (fp16 1-term) ----
#pragma unroll
        for (int kt = 0; kt < 4; ++kt) {
            int k0 = kt * 16;
            unsigned ph[4];
            ldsm4(ph, saddr(&QP[(m0w + aRow) * 72 + k0 + aCol]));
#pragma unroll
            for (int ntp = 0; ntp < 4; ++ntp) {
                int n0 = ntp * 16;
                unsigned bh[4];
                ldsm4t(bh, saddr(&Vc[(k0 + vRow) * 72 + n0 + vCol]));
                mma_f16(Oa[2 * ntp],     ph, bh);
                mma_f16(Oa[2 * ntp + 1], ph, bh + 2);
            }
        }
        // no bottom sync: next iter's top __syncthreads orders buffer reuse
    }

    // epilogue: normalize, single-round to fp16
    float invA = 1.0f / liA, invB = 1.0f / liB;
#pragma unroll
    for (int nt = 0; nt < 8; ++nt) {
        int col = nt * 8 + 2 * q4;
        size_t rA = (size_t)(qb + m0w + g) * HID + col;
        size_t rB = (size_t)(qb + m0w + 8 + g) * HID + col;
        *(unsigned*)&oh[rA] = pack2h(Oa[nt][0] * invA, Oa[nt][1] * invA);
        *(unsigned*)&oh[rB] = pack2h(Oa[nt][2] * invB, Oa[nt][3] * invB);
    }
}

// ============================================================
// launch
// ============================================================
extern "C" void kernel_launch(void* const* d_in, const int* in_sizes, int n_in,
                              void* d_out, int out_size)
{
    const float* x  = (const float*)d_in[0];
    const float* wq = (const float*)d_in[1];
    const float* wk = (const float*)d_in[2];
    const float* wv = (const float*)d_in[3];
    const float* wo = (const float*)d_in[4];
    float* out = (float*)d_out;

    float *qp, *kp, *vp;
    ushortT *xh, *wqh, *wkh, *wvh, *woh;
    ushortT *khp, *vhp, *ath;
    cudaGetSymbolAddress((void**)&qp, g_q);
    cudaGetSymbolAddress((void**)&kp, g_k);
    cudaGetSymbolAddress((void**)&vp, g_v);
    cudaGetSymbolAddress((void**)&xh, g_xh);
    cudaGetSymbolAddress((void**)&wqh, g_wqh);
    cudaGetSymbolAddress((void**)&wkh, g_wkh);
    cudaGetSymbolAddress((void**)&wvh, g_wvh);
    cudaGetSymbolAddress((void**)&woh, g_woh);
    cudaGetSymbolAddress((void**)&khp, g_kh);
    cudaGetSymbolAddress((void**)&vhp, g_vh);
    cudaGetSymbolAddress((void**)&ath, g_atth);

    dim3 blk(256);
    const int GEMM_SMEM = 2 * STG * 2;   // 46080 B

    // prep: everything -> fp16 single-rounded
    split_f16h_kernel<<<(MROWS * HID) / 1024, 256>>>(x, xh, MROWS * HID);
    split_f16h_kernel<<<(HID * HID) / 1024, 256>>>(wq, wqh, HID * HID);
    split_f16h_kernel<<<(HID * KVDIM) / 1024, 256>>>(wk, wkh, HID * KVDIM);
    split_f16h_kernel<<<(HID * KVDIM) / 1024, 256>>>(wv, wvh, HID * KVDIM);
    split_f16h_kernel<<<(HID * HID) / 1024, 256>>>(wo, woh, HID * HID);

    cudaFuncSetAttribute(gemm_f16_kernel, cudaFuncAttributeMaxDynamicSharedMemorySize, GEMM_SMEM);

    // merged QKV projection: [0,16)=Q, [16,20)=K, [20,24)=V
    gemm_f16_kernel<<<dim3(24, MROWS / 128), blk, GEMM_SMEM>>>(
        xh, wqh, wkh, wvh, qp, kp, vp,
        16, 20, HID, KVDIM, KVDIM, HID);

    // RoPE on q, k (fp32)
    int total = MROWS * NH * (HD / 2) + MROWS * KVH * (HD / 2);
    rope_kernel<<<(total + 255) / 256, 256>>>(qp, kp);

    // roped k and v -> fp16
    split_f16h_kernel<<<(MROWS * KVDIM) / 1024, 256>>>(kp, khp, MROWS * KVDIM);
    split_f16h_kernel<<<(MROWS * KVDIM) / 1024, 256>>>(vp, vhp, MROWS * KVDIM);

    // attention (emits fp16 att)
    cudaFuncSetAttribute(attn_kernel, cudaFuncAttributeMaxDynamicSharedMemorySize, 55296);
    attn_kernel<<<dim3(SEQ / 128, NH, BATCH), blk, 55296>>>(qp, khp, vhp, ath);

    // output projection -> fp32 d_out
    gemm_f16_kernel<<<dim3(16, MROWS / 128), blk, GEMM_SMEM>>>(
        ath, woh, woh, woh, out, out, out,
        16, 32, HID, HID, HID, HID);
}